// round 10
// baseline (speedup 1.0000x reference)
#include <cuda_runtime.h>
#include <math.h>

#define TT    8192
#define HH    512
#define MM    4096
#define NENT  128
#define MAXD  600
#define NF    100
#define CAP   512

// ---------------- scratch ----------------
__device__ float2 g_emb[MAXD];
__device__ int    g_cnt[2 * NENT];      // zero at load; re-zeroed by k_pair tail
__device__ int    g_done;
__device__ float4 g_clist[NENT * CAP];  // (start_bits, sc0, sc1, 0); sorted by k_sort
__device__ float4 g_dlist[NENT * CAP];
__device__ float2 g_dpm[NENT * 32];
__device__ float2 g_dsm[NENT * 32];

__device__ __forceinline__ int ldI(const void* p, int idx, int is64) {
    return is64 ? (int)((const long long*)p)[idx] : ((const int*)p)[idx];
}
__device__ __forceinline__ void fma2(unsigned long long& d, unsigned long long a,
                                     unsigned long long b) {
    asm("fma.rn.f32x2 %0, %1, %2, %0;" : "+l"(d) : "l"(a), "l"(b));
}
__device__ __forceinline__ void add2(unsigned long long& d, unsigned long long a) {
    asm("add.rn.f32x2 %0, %0, %1;" : "+l"(d) : "l"(a));
}
__device__ __forceinline__ void upk2(unsigned long long v, float& lo, float& hi) {
    asm("mov.b64 {%0, %1}, %2;" : "=f"(lo), "=f"(hi) : "l"(v));
}
__device__ __forceinline__ float tanh_fast(float x) {
    float y;
    asm("tanh.approx.f32 %0, %1;" : "=f"(y) : "f"(x));
    return y;
}

// ---------------- K1: fused span-sum + GEMM + tanh + Ws dot + bin ----------------
// 128 blocks x 640 threads (20 warps/SM). kh = tid/160 in {0..3}: k-quarter,
// 8 kk per 32-tile each. t2 = tid%160: rg = t2%16 -> rows rg+16i (i<4),
// cg = t2/16 (0..9) -> col pairs p = cg+10j (j<5). acc merged via smem tree.
#define BMM  64
#define BKK  32
#define NTH  640
#define ADP  130
#define WPAD 104
#define AS_F (BKK * ADP)                 // 4160 floats
#define WT_F (BKK * WPAD)                // 3328 floats
#define MRG_U (160 * 20)                 // 3200 u64 = 25.6 KB merge buffer
#define POOLF (AS_F + WT_F)              // 29952 B; merge (25.6KB) aliases inside

__global__ __launch_bounds__(NTH, 1) void k_mention(
        const float* __restrict__ h,
        const void* __restrict__ csp, const void* __restrict__ cent,
        const void* __restrict__ dsp, const void* __restrict__ dent,
        const float* __restrict__ Wc, const float* __restrict__ bc,
        const float* __restrict__ Wd, const float* __restrict__ bd,
        const float* __restrict__ Ws,
        const float* __restrict__ Wemb) {
    __shared__ __align__(16) float pool[POOLF];
    __shared__ int ss[BMM], se[BMM], sent[BMM];
    __shared__ int s_is64;

    float* Asd = pool;
    float* Wt  = pool + AS_F;

    int tid = threadIdx.x;
    int m0 = blockIdx.x * BMM;
    bool isC = (m0 < MM);
    const float* W  = isC ? Wc : Wd;
    const float* bb = isC ? bc : bd;
    int wsb = isC ? 0 : NF;

    if (tid < 32) {
        unsigned v = (unsigned)((const int*)csp)[1 + 2 * tid];
        unsigned any = __ballot_sync(0xffffffffu, v != 0u);
        if (tid == 0) s_is64 = (any == 0u) ? 1 : 0;
    }
    __syncthreads();
    int is64 = s_is64;
    if (tid < BMM) {
        int mi = (m0 + tid) - (isC ? 0 : MM);
        const void* sp = isC ? csp : dsp;
        const void* en = isC ? cent : dent;
        ss[tid]   = ldI(sp, 2 * mi, is64);
        se[tid]   = ldI(sp, 2 * mi + 1, is64);
        sent[tid] = ldI(en, mi, is64);
    }
    __syncthreads();

    int kh = tid / 160;          // 0..3 (warps never straddle groups)
    int t2 = tid - kh * 160;
    int rg = t2 & 15;            // rows rg + 16i
    int cg = t2 >> 4;            // 0..9
    int kh8 = kh * 8;            // kk base within tile

    // ---- A tasks: 512 tasks for tid<512 ----
    const float4* __restrict__ hp = (const float4*)h;
    bool hasA = (tid < BMM * 8);
    int r0 = (tid >> 3) & (BMM - 1), q0 = tid & 7;
    int n0 = se[r0] - ss[r0];
    const float4* p0 = hp + (size_t)ss[r0] * (HH / 4) + q0;

    // ---- W tasks: 1600 float2 over 640 threads -> 3 passes (last predicated) ----
    int kkp[3], c2p[3];
    bool hasW[3];
    #pragma unroll
    for (int p = 0; p < 3; p++) {
        int i = tid + NTH * p;
        hasW[p] = (i < BKK * 50);
        int ii = hasW[p] ? i : 0;
        kkp[p] = ii / 50;
        c2p[p] = ii - kkp[p] * 50;
    }

    unsigned long long acc[4][5];
    #pragma unroll
    for (int i = 0; i < 4; i++)
        #pragma unroll
        for (int j = 0; j < 5; j++) acc[i][j] = 0ull;

    float4 v0[8];
    float2 wr[3];

    if (hasA) {
        v0[0] = __ldg(p0);
        #pragma unroll
        for (int t = 1; t < 8; t++)
            if (t <= n0) v0[t] = __ldg(p0 + (size_t)t * (HH / 4));
    }
    #pragma unroll
    for (int p = 0; p < 3; p++)
        if (hasW[p]) wr[p] = __ldg((const float2*)&W[(size_t)kkp[p] * NF + 2 * c2p[p]]);

    for (int tile = 0; tile < HH / BKK; tile++) {
        // ---- commit prefetched regs -> smem (duplicated A) ----
        if (hasA) {
            float4 a = v0[0];
            #pragma unroll
            for (int t = 1; t < 8; t++)
                if (t <= n0) { a.x += v0[t].x; a.y += v0[t].y; a.z += v0[t].z; a.w += v0[t].w; }
            *(float2*)&Asd[(4 * q0 + 0) * ADP + 2 * r0] = make_float2(a.x, a.x);
            *(float2*)&Asd[(4 * q0 + 1) * ADP + 2 * r0] = make_float2(a.y, a.y);
            *(float2*)&Asd[(4 * q0 + 2) * ADP + 2 * r0] = make_float2(a.z, a.z);
            *(float2*)&Asd[(4 * q0 + 3) * ADP + 2 * r0] = make_float2(a.w, a.w);
        }
        #pragma unroll
        for (int p = 0; p < 3; p++)
            if (hasW[p]) *(float2*)&Wt[kkp[p] * WPAD + 2 * c2p[p]] = wr[p];
        __syncthreads();
        // ---- issue next tile's loads ----
        if (tile + 1 < HH / BKK) {
            int off = (tile + 1) * (BKK / 4);
            if (hasA) {
                v0[0] = __ldg(p0 + off);
                #pragma unroll
                for (int t = 1; t < 8; t++)
                    if (t <= n0) v0[t] = __ldg(p0 + off + (size_t)t * (HH / 4));
            }
            int kb = (tile + 1) * BKK * NF;
            #pragma unroll
            for (int p = 0; p < 3; p++)
                if (hasW[p]) wr[p] = __ldg((const float2*)&W[kb + (size_t)kkp[p] * NF + 2 * c2p[p]]);
        }
        // ---- compute: 8 kk x (4 dup-a LDS.64 + 5 w LDS.64 + 20 FFMA2) ----
        #pragma unroll
        for (int kki = 0; kki < 8; kki++) {
            int kk = kh8 + kki;
            const float* ab = &Asd[kk * ADP + 2 * rg];
            unsigned long long a0 = *(const unsigned long long*)(ab);
            unsigned long long a1 = *(const unsigned long long*)(ab + 32);
            unsigned long long a2 = *(const unsigned long long*)(ab + 64);
            unsigned long long a3 = *(const unsigned long long*)(ab + 96);
            #pragma unroll
            for (int j = 0; j < 5; j++) {
                unsigned long long w2 =
                    *(const unsigned long long*)&Wt[kk * WPAD + 2 * (cg + 10 * j)];
                fma2(acc[0][j], a0, w2);
                fma2(acc[1][j], a1, w2);
                fma2(acc[2][j], a2, w2);
                fma2(acc[3][j], a3, w2);
            }
        }
        __syncthreads();
    }

    // ---- merge 4 k-quarters through one 25.6KB smem buffer (3 stages) ----
    unsigned long long* buf = (unsigned long long*)pool;   // [160][20]
    {
        int slot = t2 * 20;
        // stage A: kh1 -> kh0
        if (kh == 1) {
            #pragma unroll
            for (int i = 0; i < 4; i++)
                #pragma unroll
                for (int j = 0; j < 5; j++) buf[slot + i * 5 + j] = acc[i][j];
        }
        __syncthreads();
        if (kh == 0) {
            #pragma unroll
            for (int i = 0; i < 4; i++)
                #pragma unroll
                for (int j = 0; j < 5; j++) add2(acc[i][j], buf[slot + i * 5 + j]);
        }
        __syncthreads();
        // stage B: kh3 -> kh2
        if (kh == 3) {
            #pragma unroll
            for (int i = 0; i < 4; i++)
                #pragma unroll
                for (int j = 0; j < 5; j++) buf[slot + i * 5 + j] = acc[i][j];
        }
        __syncthreads();
        if (kh == 2) {
            #pragma unroll
            for (int i = 0; i < 4; i++)
                #pragma unroll
                for (int j = 0; j < 5; j++) add2(acc[i][j], buf[slot + i * 5 + j]);
        }
        __syncthreads();
        // stage C: kh2 -> kh0
        if (kh == 2) {
            #pragma unroll
            for (int i = 0; i < 4; i++)
                #pragma unroll
                for (int j = 0; j < 5; j++) buf[slot + i * 5 + j] = acc[i][j];
        }
        __syncthreads();
        if (kh == 0) {
            #pragma unroll
            for (int i = 0; i < 4; i++)
                #pragma unroll
                for (int j = 0; j < 5; j++) add2(acc[i][j], buf[slot + i * 5 + j]);
        }
        __syncthreads();
    }

    // ---- epilogue on kh0 (160 threads cover 64 rows x 100 cols) ----
    float* red2 = pool;                    // [64][10][2] floats (buf is dead)
    if (kh == 0) {
        float s0[4] = {0.f, 0.f, 0.f, 0.f}, s1[4] = {0.f, 0.f, 0.f, 0.f};
        #pragma unroll
        for (int j = 0; j < 5; j++) {
            int p = cg + 10 * j, c0 = 2 * p;
            float2 bias = *(const float2*)&bb[c0];
            float2 w0 = *(const float2*)&Ws[(wsb + c0) * 2];
            float2 w1 = *(const float2*)&Ws[(wsb + c0 + 1) * 2];
            #pragma unroll
            for (int i = 0; i < 4; i++) {
                float lo, hi;
                upk2(acc[i][j], lo, hi);
                float t0 = tanh_fast(lo + bias.x);
                float t1 = tanh_fast(hi + bias.y);
                s0[i] += t0 * w0.x + t1 * w1.x;
                s1[i] += t0 * w0.y + t1 * w1.y;
            }
        }
        __syncthreads();                   // buf reads done before red2 overwrite
        #pragma unroll
        for (int i = 0; i < 4; i++) {
            int r = rg + 16 * i;
            red2[(r * 10 + cg) * 2 + 0] = s0[i];
            red2[(r * 10 + cg) * 2 + 1] = s1[i];
        }
    } else {
        __syncthreads();
    }
    __syncthreads();
    if (tid < BMM) {
        float s0 = 0.f, s1 = 0.f;
        #pragma unroll
        for (int c = 0; c < 10; c++) {
            s0 += red2[(tid * 10 + c) * 2 + 0];
            s1 += red2[(tid * 10 + c) * 2 + 1];
        }
        int ent = sent[tid];
        int pos = atomicAdd(&g_cnt[(isC ? 0 : NENT) + ent], 1);
        if (pos < CAP) {
            float4 rec;
            rec.x = __int_as_float(ss[tid]);
            rec.y = s0; rec.z = s1; rec.w = 0.f;
            (isC ? g_clist : g_dlist)[ent * CAP + pos] = rec;
        }
    }

    // blocks 0..7: emb precontract (consumed only by k_pair)
    if (blockIdx.x < 8) {
        for (int i = tid; i < 75 * 2; i += NTH) {
            int d = 75 * blockIdx.x + (i >> 1), k = i & 1;
            float a = 0.f;
            #pragma unroll
            for (int j = 0; j < 50; j++)
                a += Wemb[d * 50 + j] * Ws[(200 + j) * 2 + k];
            if (k == 0) g_emb[d].x = a; else g_emb[d].y = a;
        }
    }
}

// ---------------- K1.5: per-bin warp bitonic sort by start + prefix/suffix max ----
__global__ __launch_bounds__(256) void k_sort() {
    int gw = (blockIdx.x * blockDim.x + threadIdx.x) >> 5;
    int lane = threadIdx.x & 31;
    if (gw >= 2 * NENT) return;
    bool isD = (gw < NENT);
    int e = isD ? gw : gw - NENT;
    float4* list = isD ? &g_dlist[e * CAP] : &g_clist[e * CAP];
    int n = min(isD ? g_cnt[NENT + e] : g_cnt[e], CAP);
    if (n > 32) n = 32;

    int key = 0x7FFFFFFF;
    float py = -INFINITY, pz = -INFINITY;
    if (lane < n) {
        float4 r = list[lane];
        key = __float_as_int(r.x);
        py = r.y; pz = r.z;
    }
    #pragma unroll
    for (int k = 2; k <= 32; k <<= 1) {
        #pragma unroll
        for (int j = k >> 1; j > 0; j >>= 1) {
            int   ok = __shfl_xor_sync(0xffffffffu, key, j);
            float oy = __shfl_xor_sync(0xffffffffu, py, j);
            float oz = __shfl_xor_sync(0xffffffffu, pz, j);
            bool up = ((lane & k) == 0);
            bool lower = ((lane & j) == 0);
            bool takeMin = (lower == up);
            bool takeOther = takeMin ? (ok < key) : (ok > key);
            if (takeOther) { key = ok; py = oy; pz = oz; }
        }
    }
    float pmy = py, pmz = pz, smy = py, smz = pz;
    #pragma unroll
    for (int off = 1; off < 32; off <<= 1) {
        float t;
        t = __shfl_up_sync(0xffffffffu, pmy, off);  if (lane >= off) pmy = fmaxf(pmy, t);
        t = __shfl_up_sync(0xffffffffu, pmz, off);  if (lane >= off) pmz = fmaxf(pmz, t);
        t = __shfl_down_sync(0xffffffffu, smy, off); if (lane + off < 32) smy = fmaxf(smy, t);
        t = __shfl_down_sync(0xffffffffu, smz, off); if (lane + off < 32) smz = fmaxf(smz, t);
    }
    list[lane] = make_float4(__int_as_float(key), py, pz, 0.f);
    if (isD) {
        g_dpm[e * 32 + lane] = make_float2(pmy, pmz);
        g_dsm[e * 32 + lane] = make_float2(smy, smz);
    }
}

// ---------------- K2: windowed pairwise max + fused softmax (round-9) -------------
__global__ __launch_bounds__(256) void k_pair(const float* __restrict__ bs,
                                              float* __restrict__ out) {
    __shared__ float2 s_emb[MAXD];
    __shared__ int    s_ds[16][32];
    __shared__ float2 s_yz[16][32];
    __shared__ float2 s_pm[16][32];
    __shared__ float2 s_sm[16][32];
    int ce = blockIdx.x;
    int dg = blockIdx.y;
    int tid = threadIdx.x;
    for (int i = tid; i < MAXD; i += 256) s_emb[i] = g_emb[i];
    for (int i = tid; i < 16 * 32; i += 256) {
        int dd = i >> 5, slot = i & 31;
        int de = dg * 16 + dd;
        float4 r = g_dlist[de * CAP + slot];
        s_ds[dd][slot] = __float_as_int(r.x);
        s_yz[dd][slot] = make_float2(r.y, r.z);
        s_pm[dd][slot] = g_dpm[de * 32 + slot];
        s_sm[dd][slot] = g_dsm[de * 32 + slot];
    }
    __syncthreads();

    int lane = tid & 31, w = tid >> 5;
    int nc = min(g_cnt[ce], CAP);
    float2 e599 = s_emb[MAXD - 1];
    float bs0 = __ldg(&bs[0]), bs1 = __ldg(&bs[1]);

    float M0[2] = {-INFINITY, -INFINITY};
    float M1[2] = {-INFINITY, -INFINITY};

    for (int c0 = 0; c0 < nc; c0 += 32) {
        int ci = c0 + lane;
        float4 cr = (ci < nc) ? g_clist[ce * CAP + ci]
                              : make_float4(0.f, -INFINITY, -INFINITY, 0.f);
        int cs = __float_as_int(cr.x);
        int t1 = cs - 598, tgt2 = cs + 599;

        #pragma unroll
        for (int dit = 0; dit < 2; dit++) {
            int dd = dit * 8 + w;
            int lo = 0, hi = 0;
            #pragma unroll
            for (int s = 16; s > 0; s >>= 1) {
                if (s_ds[dd][lo + s - 1] < t1)   lo += s;
                if (s_ds[dd][hi + s - 1] < tgt2) hi += s;
            }
            if (lo < 32 && s_ds[dd][lo] < t1)   lo += 1;
            if (hi < 32 && s_ds[dd][hi] < tgt2) hi += 1;
            float lpx = (lo > 0)  ? s_pm[dd][lo - 1].x : -INFINITY;
            float lpy = (lo > 0)  ? s_pm[dd][lo - 1].y : -INFINITY;
            float rsx = (hi < 32) ? s_sm[dd][hi].x     : -INFINITY;
            float rsy = (hi < 32) ? s_sm[dd][hi].y     : -INFINITY;
            float mmx = fmaxf(lpx, rsx) + e599.x;
            float mmy = fmaxf(lpy, rsy) + e599.y;
            for (int j = lo; j < hi; j++) {
                int dsj = s_ds[dd][j];
                float2 yz = s_yz[dd][j];
                int d = abs(cs - dsj);
                float2 ev = s_emb[d];
                mmx = fmaxf(mmx, yz.x + ev.x);
                mmy = fmaxf(mmy, yz.y + ev.y);
            }
            int de = dg * 16 + dd;
            int nd = min(g_cnt[NENT + de], CAP);
            for (int j = 32; j < nd; j++) {
                float4 dr = g_dlist[de * CAP + j];
                int d = min(__usad((unsigned)cs, (unsigned)__float_as_int(dr.x), 0u),
                            (unsigned)(MAXD - 1));
                float2 ev = s_emb[d];
                mmx = fmaxf(mmx, dr.y + ev.x);
                mmy = fmaxf(mmy, dr.z + ev.y);
            }
            M0[dit] = fmaxf(M0[dit], cr.y + mmx);
            M1[dit] = fmaxf(M1[dit], cr.z + mmy);
        }
    }

    #pragma unroll
    for (int dit = 0; dit < 2; dit++) {
        float m0 = M0[dit], m1 = M1[dit];
        #pragma unroll
        for (int off = 16; off > 0; off >>= 1) {
            m0 = fmaxf(m0, __shfl_xor_sync(0xffffffffu, m0, off));
            m1 = fmaxf(m1, __shfl_xor_sync(0xffffffffu, m1, off));
        }
        if (lane == 0) {
            int de = dg * 16 + dit * 8 + w;
            float x0 = m0 + bs0, x1 = m1 + bs1;
            float mx = fmaxf(x0, x1);
            float e0 = expf(x0 - mx), e1 = expf(x1 - mx);
            float inv = 1.f / (e0 + e1);
            out[(ce * NENT + de) * 2 + 0] = e0 * inv;
            out[(ce * NENT + de) * 2 + 1] = e1 * inv;
        }
    }

    __threadfence();
    __syncthreads();
    if (tid == 0) {
        int old = atomicAdd(&g_done, 1);
        if (old == NENT * 8 - 1) {
            #pragma unroll 1
            for (int i = 0; i < 2 * NENT; i++) g_cnt[i] = 0;
            g_done = 0;
            __threadfence();
        }
    }
}

// ---------------- launch ----------------
extern "C" void kernel_launch(void* const* d_in, const int* in_sizes, int n_in,
                              void* d_out, int out_size) {
    const float* h    = (const float*)d_in[0];
    const void*  csp  = d_in[1];
    const void*  cent = d_in[2];
    const void*  dsp  = d_in[3];
    const void*  dent = d_in[4];
    const float* Wc   = (const float*)d_in[5];
    const float* bc   = (const float*)d_in[6];
    const float* Wd   = (const float*)d_in[7];
    const float* bd   = (const float*)d_in[8];
    const float* Wemb = (const float*)d_in[9];
    const float* Ws   = (const float*)d_in[10];
    const float* bs   = (const float*)d_in[11];
    float* out = (float*)d_out;

    k_mention<<<2 * MM / BMM, NTH>>>(h, csp, cent, dsp, dent, Wc, bc, Wd, bd, Ws, Wemb);
    k_sort<<<32, 256>>>();
    k_pair<<<dim3(NENT, 8), 256>>>(bs, out);
}

// round 11
// speedup vs baseline: 1.0488x; 1.0488x over previous
#include <cuda_runtime.h>
#include <math.h>

#define TT    8192
#define HH    512
#define MM    4096
#define NENT  128
#define MAXD  600
#define NF    100
#define CAP   512

// ---------------- scratch ----------------
__device__ float2 g_emb[MAXD];
__device__ int    g_cnt[2 * NENT];      // zero at load; re-zeroed by k_pair tail
__device__ int    g_done;
__device__ float4 g_clist[NENT * CAP];  // (start_bits, sc0, sc1, 0); sorted by k_sort
__device__ float4 g_dlist[NENT * CAP];
__device__ float2 g_dpm[NENT * 32];
__device__ float2 g_dsm[NENT * 32];

__device__ __forceinline__ int ldI(const void* p, int idx, int is64) {
    return is64 ? (int)((const long long*)p)[idx] : ((const int*)p)[idx];
}
__device__ __forceinline__ void fma2(unsigned long long& d, unsigned long long a,
                                     unsigned long long b) {
    asm("fma.rn.f32x2 %0, %1, %2, %0;" : "+l"(d) : "l"(a), "l"(b));
}
__device__ __forceinline__ void upk2(unsigned long long v, float& lo, float& hi) {
    asm("mov.b64 {%0, %1}, %2;" : "=f"(lo), "=f"(hi) : "l"(v));
}
__device__ __forceinline__ float tanh_fast(float x) {
    float y;
    asm("tanh.approx.f32 %0, %1;" : "=f"(y) : "f"(x));
    return y;
}

// ---------------- K1: fused span-sum + GEMM + tanh + Ws dot + bin ----------------
// 256 blocks (BMM=32 mentions), 320 threads, 2 CTAs/SM (phase interleaving).
// kh = tid/160 (k half, 16 kk each), t2 = tid%160: rg = t2%16 -> rows rg, rg+16;
// cg = t2/16 (0..9) -> col pairs p = cg+10j (j<5).
// A stored transposed + duplicated: Asd[kk][2r]=Asd[kk][2r+1]=a(r,kk); dup LDS.64
// feeds FFMA2 directly, conflict-free across 16 rg lanes (broadcast for 2nd cg).
#define BMM  32
#define BKK  32
#define NTH  320
#define ADP  66                          // dup-A float stride per kk
#define WPAD 104
#define AS_F (BKK * ADP)                 // 2112 floats
#define WT_F (BKK * WPAD)                // 3328 floats
#define POOLF (AS_F + WT_F)              // 5440 floats = 21.8 KB

__global__ __launch_bounds__(NTH, 2) void k_mention(
        const float* __restrict__ h,
        const void* __restrict__ csp, const void* __restrict__ cent,
        const void* __restrict__ dsp, const void* __restrict__ dent,
        const float* __restrict__ Wc, const float* __restrict__ bc,
        const float* __restrict__ Wd, const float* __restrict__ bd,
        const float* __restrict__ Ws,
        const float* __restrict__ Wemb) {
    __shared__ __align__(16) float pool[POOLF];
    __shared__ int ss[BMM], se[BMM], sent[BMM];
    __shared__ int s_is64;

    float* Asd = pool;
    float* Wt  = pool + AS_F;

    int tid = threadIdx.x;
    int m0 = blockIdx.x * BMM;
    bool isC = (m0 < MM);
    const float* W  = isC ? Wc : Wd;
    const float* bb = isC ? bc : bd;
    int wsb = isC ? 0 : NF;

    if (tid < 32) {
        unsigned v = (unsigned)((const int*)csp)[1 + 2 * tid];
        unsigned any = __ballot_sync(0xffffffffu, v != 0u);
        if (tid == 0) s_is64 = (any == 0u) ? 1 : 0;
    }
    __syncthreads();
    int is64 = s_is64;
    if (tid < BMM) {
        int mi = (m0 + tid) - (isC ? 0 : MM);
        const void* sp = isC ? csp : dsp;
        const void* en = isC ? cent : dent;
        ss[tid]   = ldI(sp, 2 * mi, is64);
        se[tid]   = ldI(sp, 2 * mi + 1, is64);
        sent[tid] = ldI(en, mi, is64);
    }
    __syncthreads();

    int kh = tid / 160;          // 0..1 (warps never straddle groups)
    int t2 = tid - kh * 160;
    int rg = t2 & 15;            // rows rg, rg+16
    int cg = t2 >> 4;            // 0..9
    int kh16 = kh * 16;

    // ---- A tasks: 256 tasks for tid<256 (row r0, float4-col q0) ----
    const float4* __restrict__ hp = (const float4*)h;
    bool hasA = (tid < BMM * 8);
    int r0 = (tid >> 3) & (BMM - 1), q0 = tid & 7;
    int n0 = se[r0] - ss[r0];
    const float4* p0 = hp + (size_t)ss[r0] * (HH / 4) + q0;

    // ---- W tasks: 1600 float2 over 320 threads = 5 each ----
    int kkp[5], c2p[5];
    #pragma unroll
    for (int p = 0; p < 5; p++) {
        int i = tid + NTH * p;
        kkp[p] = i / 50;
        c2p[p] = i - kkp[p] * 50;
    }

    unsigned long long acc[2][5];
    #pragma unroll
    for (int i = 0; i < 2; i++)
        #pragma unroll
        for (int j = 0; j < 5; j++) acc[i][j] = 0ull;

    float4 v0[8];
    float2 wr[5];

    // prologue: issue loads for tile 0 (span loads predicated)
    if (hasA) {
        v0[0] = __ldg(p0);
        #pragma unroll
        for (int t = 1; t < 8; t++)
            if (t <= n0) v0[t] = __ldg(p0 + (size_t)t * (HH / 4));
    }
    #pragma unroll
    for (int p = 0; p < 5; p++)
        wr[p] = __ldg((const float2*)&W[(size_t)kkp[p] * NF + 2 * c2p[p]]);

    for (int tile = 0; tile < HH / BKK; tile++) {
        // ---- commit prefetched regs -> smem (duplicated A) ----
        if (hasA) {
            float4 a = v0[0];
            #pragma unroll
            for (int t = 1; t < 8; t++)
                if (t <= n0) { a.x += v0[t].x; a.y += v0[t].y; a.z += v0[t].z; a.w += v0[t].w; }
            *(float2*)&Asd[(4 * q0 + 0) * ADP + 2 * r0] = make_float2(a.x, a.x);
            *(float2*)&Asd[(4 * q0 + 1) * ADP + 2 * r0] = make_float2(a.y, a.y);
            *(float2*)&Asd[(4 * q0 + 2) * ADP + 2 * r0] = make_float2(a.z, a.z);
            *(float2*)&Asd[(4 * q0 + 3) * ADP + 2 * r0] = make_float2(a.w, a.w);
        }
        #pragma unroll
        for (int p = 0; p < 5; p++)
            *(float2*)&Wt[kkp[p] * WPAD + 2 * c2p[p]] = wr[p];
        __syncthreads();
        // ---- issue next tile's loads (in flight during compute) ----
        if (tile + 1 < HH / BKK) {
            int off = (tile + 1) * (BKK / 4);
            if (hasA) {
                v0[0] = __ldg(p0 + off);
                #pragma unroll
                for (int t = 1; t < 8; t++)
                    if (t <= n0) v0[t] = __ldg(p0 + off + (size_t)t * (HH / 4));
            }
            int kb = (tile + 1) * BKK * NF;
            #pragma unroll
            for (int p = 0; p < 5; p++)
                wr[p] = __ldg((const float2*)&W[kb + (size_t)kkp[p] * NF + 2 * c2p[p]]);
        }
        // ---- compute: 16 kk x (2 dup-a LDS.64 + 5 w LDS.64 + 10 FFMA2) ----
        #pragma unroll
        for (int kki = 0; kki < 16; kki++) {
            int kk = kh16 + kki;
            const float* ab = &Asd[kk * ADP + 2 * rg];
            unsigned long long a0 = *(const unsigned long long*)(ab);
            unsigned long long a1 = *(const unsigned long long*)(ab + 32);
            #pragma unroll
            for (int j = 0; j < 5; j++) {
                unsigned long long w2 =
                    *(const unsigned long long*)&Wt[kk * WPAD + 2 * (cg + 10 * j)];
                fma2(acc[0][j], a0, w2);
                fma2(acc[1][j], a1, w2);
            }
        }
        __syncthreads();   // WAR: next commit overwrites Asd/Wt
    }

    // ---- merge k-halves + epilogue (alias pool; tile reads done) ----
    float2* red  = (float2*)pool;          // [32][50]
    float*  red2 = pool + 2 * BMM * 50;    // [32][10][2] at float offset 3200

    if (kh == 0) {
        #pragma unroll
        for (int i = 0; i < 2; i++)
            #pragma unroll
            for (int j = 0; j < 5; j++) {
                float lo, hi;
                upk2(acc[i][j], lo, hi);
                red[(rg + 16 * i) * 50 + (cg + 10 * j)] = make_float2(lo, hi);
            }
    }
    __syncthreads();
    if (kh == 1) {
        float s0[2] = {0.f, 0.f}, s1[2] = {0.f, 0.f};
        #pragma unroll
        for (int j = 0; j < 5; j++) {
            int p = cg + 10 * j, c0 = 2 * p;
            float2 bias = *(const float2*)&bb[c0];
            float2 w0 = *(const float2*)&Ws[(wsb + c0) * 2];
            float2 w1 = *(const float2*)&Ws[(wsb + c0 + 1) * 2];
            #pragma unroll
            for (int i = 0; i < 2; i++) {
                float lo, hi;
                upk2(acc[i][j], lo, hi);
                float2 o = red[(rg + 16 * i) * 50 + p];
                float t0 = tanh_fast(lo + o.x + bias.x);
                float t1 = tanh_fast(hi + o.y + bias.y);
                s0[i] += t0 * w0.x + t1 * w1.x;
                s1[i] += t0 * w0.y + t1 * w1.y;
            }
        }
        #pragma unroll
        for (int i = 0; i < 2; i++) {
            int r = rg + 16 * i;
            red2[(r * 10 + cg) * 2 + 0] = s0[i];
            red2[(r * 10 + cg) * 2 + 1] = s1[i];
        }
    }
    __syncthreads();
    if (tid < BMM) {
        float s0 = 0.f, s1 = 0.f;
        #pragma unroll
        for (int c = 0; c < 10; c++) {
            s0 += red2[(tid * 10 + c) * 2 + 0];
            s1 += red2[(tid * 10 + c) * 2 + 1];
        }
        int ent = sent[tid];
        int pos = atomicAdd(&g_cnt[(isC ? 0 : NENT) + ent], 1);
        if (pos < CAP) {
            float4 rec;
            rec.x = __int_as_float(ss[tid]);
            rec.y = s0; rec.z = s1; rec.w = 0.f;
            (isC ? g_clist : g_dlist)[ent * CAP + pos] = rec;
        }
    }

    // blocks 0..7: emb precontract (consumed only by k_pair)
    if (blockIdx.x < 8) {
        for (int i = tid; i < 75 * 2; i += NTH) {
            int d = 75 * blockIdx.x + (i >> 1), k = i & 1;
            float a = 0.f;
            #pragma unroll
            for (int j = 0; j < 50; j++)
                a += Wemb[d * 50 + j] * Ws[(200 + j) * 2 + k];
            if (k == 0) g_emb[d].x = a; else g_emb[d].y = a;
        }
    }
}

// ---------------- K1.5: per-bin warp bitonic sort by start + prefix/suffix max ----
__global__ __launch_bounds__(256) void k_sort() {
    int gw = (blockIdx.x * blockDim.x + threadIdx.x) >> 5;
    int lane = threadIdx.x & 31;
    if (gw >= 2 * NENT) return;
    bool isD = (gw < NENT);
    int e = isD ? gw : gw - NENT;
    float4* list = isD ? &g_dlist[e * CAP] : &g_clist[e * CAP];
    int n = min(isD ? g_cnt[NENT + e] : g_cnt[e], CAP);
    if (n > 32) n = 32;

    int key = 0x7FFFFFFF;
    float py = -INFINITY, pz = -INFINITY;
    if (lane < n) {
        float4 r = list[lane];
        key = __float_as_int(r.x);
        py = r.y; pz = r.z;
    }
    #pragma unroll
    for (int k = 2; k <= 32; k <<= 1) {
        #pragma unroll
        for (int j = k >> 1; j > 0; j >>= 1) {
            int   ok = __shfl_xor_sync(0xffffffffu, key, j);
            float oy = __shfl_xor_sync(0xffffffffu, py, j);
            float oz = __shfl_xor_sync(0xffffffffu, pz, j);
            bool up = ((lane & k) == 0);
            bool lower = ((lane & j) == 0);
            bool takeMin = (lower == up);
            bool takeOther = takeMin ? (ok < key) : (ok > key);
            if (takeOther) { key = ok; py = oy; pz = oz; }
        }
    }
    float pmy = py, pmz = pz, smy = py, smz = pz;
    #pragma unroll
    for (int off = 1; off < 32; off <<= 1) {
        float t;
        t = __shfl_up_sync(0xffffffffu, pmy, off);  if (lane >= off) pmy = fmaxf(pmy, t);
        t = __shfl_up_sync(0xffffffffu, pmz, off);  if (lane >= off) pmz = fmaxf(pmz, t);
        t = __shfl_down_sync(0xffffffffu, smy, off); if (lane + off < 32) smy = fmaxf(smy, t);
        t = __shfl_down_sync(0xffffffffu, smz, off); if (lane + off < 32) smz = fmaxf(smz, t);
    }
    list[lane] = make_float4(__int_as_float(key), py, pz, 0.f);
    if (isD) {
        g_dpm[e * 32 + lane] = make_float2(pmy, pmz);
        g_dsm[e * 32 + lane] = make_float2(smy, smz);
    }
}

// ---------------- K2: windowed pairwise max + fused softmax ----------------------
__global__ __launch_bounds__(256) void k_pair(const float* __restrict__ bs,
                                              float* __restrict__ out) {
    __shared__ float2 s_emb[MAXD];
    __shared__ int    s_ds[16][32];
    __shared__ float2 s_yz[16][32];
    __shared__ float2 s_pm[16][32];
    __shared__ float2 s_sm[16][32];
    int ce = blockIdx.x;
    int dg = blockIdx.y;
    int tid = threadIdx.x;
    for (int i = tid; i < MAXD; i += 256) s_emb[i] = g_emb[i];
    for (int i = tid; i < 16 * 32; i += 256) {
        int dd = i >> 5, slot = i & 31;
        int de = dg * 16 + dd;
        float4 r = g_dlist[de * CAP + slot];
        s_ds[dd][slot] = __float_as_int(r.x);
        s_yz[dd][slot] = make_float2(r.y, r.z);
        s_pm[dd][slot] = g_dpm[de * 32 + slot];
        s_sm[dd][slot] = g_dsm[de * 32 + slot];
    }
    __syncthreads();

    int lane = tid & 31, w = tid >> 5;
    int nc = min(g_cnt[ce], CAP);
    float2 e599 = s_emb[MAXD - 1];
    float bs0 = __ldg(&bs[0]), bs1 = __ldg(&bs[1]);

    float M0[2] = {-INFINITY, -INFINITY};
    float M1[2] = {-INFINITY, -INFINITY};

    for (int c0 = 0; c0 < nc; c0 += 32) {
        int ci = c0 + lane;
        float4 cr = (ci < nc) ? g_clist[ce * CAP + ci]
                              : make_float4(0.f, -INFINITY, -INFINITY, 0.f);
        int cs = __float_as_int(cr.x);
        int t1 = cs - 598, tgt2 = cs + 599;

        #pragma unroll
        for (int dit = 0; dit < 2; dit++) {
            int dd = dit * 8 + w;
            int lo = 0, hi = 0;
            #pragma unroll
            for (int s = 16; s > 0; s >>= 1) {
                if (s_ds[dd][lo + s - 1] < t1)   lo += s;
                if (s_ds[dd][hi + s - 1] < tgt2) hi += s;
            }
            if (lo < 32 && s_ds[dd][lo] < t1)   lo += 1;
            if (hi < 32 && s_ds[dd][hi] < tgt2) hi += 1;
            float lpx = (lo > 0)  ? s_pm[dd][lo - 1].x : -INFINITY;
            float lpy = (lo > 0)  ? s_pm[dd][lo - 1].y : -INFINITY;
            float rsx = (hi < 32) ? s_sm[dd][hi].x     : -INFINITY;
            float rsy = (hi < 32) ? s_sm[dd][hi].y     : -INFINITY;
            float mmx = fmaxf(lpx, rsx) + e599.x;
            float mmy = fmaxf(lpy, rsy) + e599.y;
            for (int j = lo; j < hi; j++) {
                int dsj = s_ds[dd][j];
                float2 yz = s_yz[dd][j];
                int d = abs(cs - dsj);
                float2 ev = s_emb[d];
                mmx = fmaxf(mmx, yz.x + ev.x);
                mmy = fmaxf(mmy, yz.y + ev.y);
            }
            int de = dg * 16 + dd;
            int nd = min(g_cnt[NENT + de], CAP);
            for (int j = 32; j < nd; j++) {
                float4 dr = g_dlist[de * CAP + j];
                int d = min(__usad((unsigned)cs, (unsigned)__float_as_int(dr.x), 0u),
                            (unsigned)(MAXD - 1));
                float2 ev = s_emb[d];
                mmx = fmaxf(mmx, dr.y + ev.x);
                mmy = fmaxf(mmy, dr.z + ev.y);
            }
            M0[dit] = fmaxf(M0[dit], cr.y + mmx);
            M1[dit] = fmaxf(M1[dit], cr.z + mmy);
        }
    }

    #pragma unroll
    for (int dit = 0; dit < 2; dit++) {
        float m0 = M0[dit], m1 = M1[dit];
        #pragma unroll
        for (int off = 16; off > 0; off >>= 1) {
            m0 = fmaxf(m0, __shfl_xor_sync(0xffffffffu, m0, off));
            m1 = fmaxf(m1, __shfl_xor_sync(0xffffffffu, m1, off));
        }
        if (lane == 0) {
            int de = dg * 16 + dit * 8 + w;
            float x0 = m0 + bs0, x1 = m1 + bs1;
            float mx = fmaxf(x0, x1);
            float e0 = expf(x0 - mx), e1 = expf(x1 - mx);
            float inv = 1.f / (e0 + e1);
            out[(ce * NENT + de) * 2 + 0] = e0 * inv;
            out[(ce * NENT + de) * 2 + 1] = e1 * inv;
        }
    }

    __threadfence();
    __syncthreads();
    if (tid == 0) {
        int old = atomicAdd(&g_done, 1);
        if (old == NENT * 8 - 1) {
            #pragma unroll 1
            for (int i = 0; i < 2 * NENT; i++) g_cnt[i] = 0;
            g_done = 0;
            __threadfence();
        }
    }
}

// ---------------- launch ----------------
extern "C" void kernel_launch(void* const* d_in, const int* in_sizes, int n_in,
                              void* d_out, int out_size) {
    const float* h    = (const float*)d_in[0];
    const void*  csp  = d_in[1];
    const void*  cent = d_in[2];
    const void*  dsp  = d_in[3];
    const void*  dent = d_in[4];
    const float* Wc   = (const float*)d_in[5];
    const float* bc   = (const float*)d_in[6];
    const float* Wd   = (const float*)d_in[7];
    const float* bd   = (const float*)d_in[8];
    const float* Wemb = (const float*)d_in[9];
    const float* Ws   = (const float*)d_in[10];
    const float* bs   = (const float*)d_in[11];
    float* out = (float*)d_out;

    k_mention<<<2 * MM / BMM, NTH>>>(h, csp, cent, dsp, dent, Wc, bc, Wd, bd, Ws, Wemb);
    k_sort<<<32, 256>>>();
    k_pair<<<dim3(NENT, 8), 256>>>(bs, out);
}

// round 12
// speedup vs baseline: 1.0719x; 1.0220x over previous
#include <cuda_runtime.h>
#include <math.h>

#define TT    8192
#define HH    512
#define MM    4096
#define NENT  128
#define MAXD  600
#define NF    100
#define CAP   512

// ---------------- scratch ----------------
__device__ float2 g_emb[MAXD];
__device__ int    g_cnt[2 * NENT];      // zero at load; re-zeroed by k_pair tail
__device__ int    g_done;
__device__ float4 g_clist[NENT * CAP];  // (start_bits, sc0, sc1, 0); sorted by k_sort
__device__ float4 g_dlist[NENT * CAP];
__device__ float2 g_dpm[NENT * 32];
__device__ float2 g_dsm[NENT * 32];

__device__ __forceinline__ int ldI(const void* p, int idx, int is64) {
    return is64 ? (int)((const long long*)p)[idx] : ((const int*)p)[idx];
}
__device__ __forceinline__ void fma2(unsigned long long& d, unsigned long long a,
                                     unsigned long long b) {
    asm("fma.rn.f32x2 %0, %1, %2, %0;" : "+l"(d) : "l"(a), "l"(b));
}
__device__ __forceinline__ void add2(unsigned long long& d, unsigned long long a) {
    asm("add.rn.f32x2 %0, %0, %1;" : "+l"(d) : "l"(a));
}
__device__ __forceinline__ void upk2(unsigned long long v, float& lo, float& hi) {
    asm("mov.b64 {%0, %1}, %2;" : "=f"(lo), "=f"(hi) : "l"(v));
}
__device__ __forceinline__ float tanh_fast(float x) {
    float y;
    asm("tanh.approx.f32 %0, %1;" : "=f"(y) : "f"(x));
    return y;
}
#define CP_ASYNC16(dst, src) \
    asm volatile("cp.async.ca.shared.global [%0], [%1], 16;" :: "r"(dst), "l"(src))
#define CP_COMMIT()  asm volatile("cp.async.commit_group;")
#define CP_WAIT1()   asm volatile("cp.async.wait_group 1;")

// ---------------- K1: fused span-sum + GEMM + tanh + Ws dot + bin ----------------
// 256 blocks (BMM=32), 320 threads, 2 CTAs/SM. 4 kh-groups of 80 threads
// (8 kk per 32-k tile each). t2 = tid%80: rg = t2%8 -> rows rg+8i (i<4),
// cg = t2/8 (0..9) -> col pairs p = cg+10j (j<5). Thread tile 4x5:
// per kk: 4 dup-a LDS.64 + 5 w LDS.64 + 20 FFMA2 (0.45 wf/FFMA2).
// A: register prefetch (span-predicated LDG) -> dup STS. W: cp.async double-buffer.
#define BMM  32
#define BKK  32
#define NTH  320
#define NT   (HH / BKK)                  // 16 tiles
#define ADP  66                          // dup-A float stride per kk
#define WPAD 104
#define AS_F (BKK * ADP)                 // 2112 floats
#define WT_F (BKK * WPAD)                // 3328 floats per W buffer
#define POOLF (AS_F + 2 * WT_F)          // 8768 floats = 35 KB

__global__ __launch_bounds__(NTH, 2) void k_mention(
        const float* __restrict__ h,
        const void* __restrict__ csp, const void* __restrict__ cent,
        const void* __restrict__ dsp, const void* __restrict__ dent,
        const float* __restrict__ Wc, const float* __restrict__ bc,
        const float* __restrict__ Wd, const float* __restrict__ bd,
        const float* __restrict__ Ws,
        const float* __restrict__ Wemb) {
    __shared__ __align__(16) float pool[POOLF];
    __shared__ int ss[BMM], se[BMM], sent[BMM];
    __shared__ int s_is64;

    float* Asd = pool;                        // single-buffered A (dup layout)
    float* Wt  = pool + AS_F;                 // double-buffered W

    int tid = threadIdx.x;
    int m0 = blockIdx.x * BMM;
    bool isC = (m0 < MM);
    const float* W  = isC ? Wc : Wd;
    const float* bb = isC ? bc : bd;
    int wsb = isC ? 0 : NF;

    if (tid < 32) {
        unsigned v = (unsigned)((const int*)csp)[1 + 2 * tid];
        unsigned any = __ballot_sync(0xffffffffu, v != 0u);
        if (tid == 0) s_is64 = (any == 0u) ? 1 : 0;
    }
    __syncthreads();
    int is64 = s_is64;
    if (tid < BMM) {
        int mi = (m0 + tid) - (isC ? 0 : MM);
        const void* sp = isC ? csp : dsp;
        const void* en = isC ? cent : dent;
        ss[tid]   = ldI(sp, 2 * mi, is64);
        se[tid]   = ldI(sp, 2 * mi + 1, is64);
        sent[tid] = ldI(en, mi, is64);
    }
    __syncthreads();

    int kh = tid / 80;           // 0..3 k-quarter
    int t2 = tid - kh * 80;
    int rg = t2 & 7;             // rows rg + 8i
    int cg = t2 >> 3;            // 0..9
    int kh8 = kh * 8;

    // ---- A tasks: 256 float4 tasks, one per thread (tid<256) ----
    const float4* __restrict__ hp = (const float4*)h;
    bool hasA = (tid < BMM * 8);
    int r0 = (tid >> 3) & (BMM - 1), q0 = tid & 7;
    int n0 = se[r0] - ss[r0];
    const float4* p0 = hp + (size_t)ss[r0] * (HH / 4) + q0;

    // ---- W cp.async tasks: 800 16B-chunks / 320 threads (<=3 each) ----
    unsigned wt_base;
    {
        unsigned long long gen = (unsigned long long)__cvta_generic_to_shared(Wt);
        wt_base = (unsigned)gen;
    }
    int wsrc[3];                 // float offset within W tile row-space
    unsigned wdst[3];            // byte offset within one Wt buffer
    bool hasW[3];
    #pragma unroll
    for (int p = 0; p < 3; p++) {
        int i = tid + NTH * p;
        hasW[p] = (i < 800);
        int ii = hasW[p] ? i : 0;
        int kk = ii / 25, c4 = ii - kk * 25;
        wsrc[p] = kk * NF + 4 * c4;
        wdst[p] = (unsigned)((kk * WPAD + 4 * c4) * 4);
    }

    unsigned long long acc[4][5];
    #pragma unroll
    for (int i = 0; i < 4; i++)
        #pragma unroll
        for (int j = 0; j < 5; j++) acc[i][j] = 0ull;

    float4 v0[8];

    // prologue: W(0) async, A(0) regs
    #pragma unroll
    for (int p = 0; p < 3; p++)
        if (hasW[p]) CP_ASYNC16(wt_base + wdst[p], &W[wsrc[p]]);
    CP_COMMIT();
    if (hasA) {
        v0[0] = __ldg(p0);
        #pragma unroll
        for (int t = 1; t < 8; t++)
            if (t <= n0) v0[t] = __ldg(p0 + (size_t)t * (HH / 4));
    }

    for (int tile = 0; tile < NT; tile++) {
        // ---- commit A(tile): reduce prefetched regs -> dup smem ----
        if (hasA) {
            float4 a = v0[0];
            #pragma unroll
            for (int t = 1; t < 8; t++)
                if (t <= n0) { a.x += v0[t].x; a.y += v0[t].y; a.z += v0[t].z; a.w += v0[t].w; }
            *(float2*)&Asd[(4 * q0 + 0) * ADP + 2 * r0] = make_float2(a.x, a.x);
            *(float2*)&Asd[(4 * q0 + 1) * ADP + 2 * r0] = make_float2(a.y, a.y);
            *(float2*)&Asd[(4 * q0 + 2) * ADP + 2 * r0] = make_float2(a.z, a.z);
            *(float2*)&Asd[(4 * q0 + 3) * ADP + 2 * r0] = make_float2(a.w, a.w);
        }
        // ---- issue W(tile+1) async into the other buffer ----
        if (tile + 1 < NT) {
            int kb = (tile + 1) * BKK * NF;
            unsigned bofs = ((tile + 1) & 1) ? (unsigned)(WT_F * 4) : 0u;
            #pragma unroll
            for (int p = 0; p < 3; p++)
                if (hasW[p]) CP_ASYNC16(wt_base + bofs + wdst[p], &W[kb + wsrc[p]]);
        }
        CP_COMMIT();
        CP_WAIT1();              // W(tile) landed (this thread's chunks)
        __syncthreads();         // all threads' A(tile) + W(tile) visible
        // ---- issue A(tile+1) LDGs (in flight during compute) ----
        if (tile + 1 < NT && hasA) {
            int off = (tile + 1) * (BKK / 4);
            v0[0] = __ldg(p0 + off);
            #pragma unroll
            for (int t = 1; t < 8; t++)
                if (t <= n0) v0[t] = __ldg(p0 + off + (size_t)t * (HH / 4));
        }
        // ---- compute: 8 kk x (4 dup-a LDS.64 + 5 w LDS.64 + 20 FFMA2) ----
        const float* Wtb = Wt + (tile & 1) * WT_F;
        #pragma unroll
        for (int kki = 0; kki < 8; kki++) {
            int kk = kh8 + kki;
            const float* ab = &Asd[kk * ADP + 2 * rg];
            unsigned long long a0 = *(const unsigned long long*)(ab);
            unsigned long long a1 = *(const unsigned long long*)(ab + 16);
            unsigned long long a2 = *(const unsigned long long*)(ab + 32);
            unsigned long long a3 = *(const unsigned long long*)(ab + 48);
            #pragma unroll
            for (int j = 0; j < 5; j++) {
                unsigned long long w2 =
                    *(const unsigned long long*)&Wtb[kk * WPAD + 2 * (cg + 10 * j)];
                fma2(acc[0][j], a0, w2);
                fma2(acc[1][j], a1, w2);
                fma2(acc[2][j], a2, w2);
                fma2(acc[3][j], a3, w2);
            }
        }
        __syncthreads();         // WAR: next commit overwrites Asd
    }

    // ---- merge 4 k-quarters (kh1->kh0, kh3->kh2, then kh2->kh0) ----
    unsigned long long* buf = (unsigned long long*)pool;   // [160][20] u64 = 25.6 KB
    {
        int slotA = t2 * 20;             // groups 0/1 region
        int slotB = (80 + t2) * 20;      // groups 2/3 region
        if (kh == 1) {
            #pragma unroll
            for (int i = 0; i < 4; i++)
                #pragma unroll
                for (int j = 0; j < 5; j++) buf[slotA + i * 5 + j] = acc[i][j];
        }
        if (kh == 3) {
            #pragma unroll
            for (int i = 0; i < 4; i++)
                #pragma unroll
                for (int j = 0; j < 5; j++) buf[slotB + i * 5 + j] = acc[i][j];
        }
        __syncthreads();
        if (kh == 0) {
            #pragma unroll
            for (int i = 0; i < 4; i++)
                #pragma unroll
                for (int j = 0; j < 5; j++) add2(acc[i][j], buf[slotA + i * 5 + j]);
        }
        if (kh == 2) {
            #pragma unroll
            for (int i = 0; i < 4; i++)
                #pragma unroll
                for (int j = 0; j < 5; j++) add2(acc[i][j], buf[slotB + i * 5 + j]);
        }
        __syncthreads();
        if (kh == 2) {
            #pragma unroll
            for (int i = 0; i < 4; i++)
                #pragma unroll
                for (int j = 0; j < 5; j++) buf[slotA + i * 5 + j] = acc[i][j];
        }
        __syncthreads();
        if (kh == 0) {
            #pragma unroll
            for (int i = 0; i < 4; i++)
                #pragma unroll
                for (int j = 0; j < 5; j++) add2(acc[i][j], buf[slotA + i * 5 + j]);
        }
        __syncthreads();                 // buf dead; pool reusable
    }

    // ---- epilogue on kh0 (80 threads cover 32 rows x 100 cols) ----
    float* red2 = pool;                  // [32][10][2] floats
    if (kh == 0) {
        float s0[4] = {0.f, 0.f, 0.f, 0.f}, s1[4] = {0.f, 0.f, 0.f, 0.f};
        #pragma unroll
        for (int j = 0; j < 5; j++) {
            int p = cg + 10 * j, c0 = 2 * p;
            float2 bias = *(const float2*)&bb[c0];
            float2 w0 = *(const float2*)&Ws[(wsb + c0) * 2];
            float2 w1 = *(const float2*)&Ws[(wsb + c0 + 1) * 2];
            #pragma unroll
            for (int i = 0; i < 4; i++) {
                float lo, hi;
                upk2(acc[i][j], lo, hi);
                float t0 = tanh_fast(lo + bias.x);
                float t1 = tanh_fast(hi + bias.y);
                s0[i] += t0 * w0.x + t1 * w1.x;
                s1[i] += t0 * w0.y + t1 * w1.y;
            }
        }
        #pragma unroll
        for (int i = 0; i < 4; i++) {
            int r = rg + 8 * i;
            red2[(r * 10 + cg) * 2 + 0] = s0[i];
            red2[(r * 10 + cg) * 2 + 1] = s1[i];
        }
    }
    __syncthreads();
    if (tid < BMM) {
        float s0 = 0.f, s1 = 0.f;
        #pragma unroll
        for (int c = 0; c < 10; c++) {
            s0 += red2[(tid * 10 + c) * 2 + 0];
            s1 += red2[(tid * 10 + c) * 2 + 1];
        }
        int ent = sent[tid];
        int pos = atomicAdd(&g_cnt[(isC ? 0 : NENT) + ent], 1);
        if (pos < CAP) {
            float4 rec;
            rec.x = __int_as_float(ss[tid]);
            rec.y = s0; rec.z = s1; rec.w = 0.f;
            (isC ? g_clist : g_dlist)[ent * CAP + pos] = rec;
        }
    }

    // blocks 0..7: emb precontract (consumed only by k_pair)
    if (blockIdx.x < 8) {
        for (int i = tid; i < 75 * 2; i += NTH) {
            int d = 75 * blockIdx.x + (i >> 1), k = i & 1;
            float a = 0.f;
            #pragma unroll
            for (int j = 0; j < 50; j++)
                a += Wemb[d * 50 + j] * Ws[(200 + j) * 2 + k];
            if (k == 0) g_emb[d].x = a; else g_emb[d].y = a;
        }
    }
}

// ---------------- K1.5: per-bin warp bitonic sort by start + prefix/suffix max ----
__global__ __launch_bounds__(256) void k_sort() {
    int gw = (blockIdx.x * blockDim.x + threadIdx.x) >> 5;
    int lane = threadIdx.x & 31;
    if (gw >= 2 * NENT) return;
    bool isD = (gw < NENT);
    int e = isD ? gw : gw - NENT;
    float4* list = isD ? &g_dlist[e * CAP] : &g_clist[e * CAP];
    int n = min(isD ? g_cnt[NENT + e] : g_cnt[e], CAP);
    if (n > 32) n = 32;

    int key = 0x7FFFFFFF;
    float py = -INFINITY, pz = -INFINITY;
    if (lane < n) {
        float4 r = list[lane];
        key = __float_as_int(r.x);
        py = r.y; pz = r.z;
    }
    #pragma unroll
    for (int k = 2; k <= 32; k <<= 1) {
        #pragma unroll
        for (int j = k >> 1; j > 0; j >>= 1) {
            int   ok = __shfl_xor_sync(0xffffffffu, key, j);
            float oy = __shfl_xor_sync(0xffffffffu, py, j);
            float oz = __shfl_xor_sync(0xffffffffu, pz, j);
            bool up = ((lane & k) == 0);
            bool lower = ((lane & j) == 0);
            bool takeMin = (lower == up);
            bool takeOther = takeMin ? (ok < key) : (ok > key);
            if (takeOther) { key = ok; py = oy; pz = oz; }
        }
    }
    float pmy = py, pmz = pz, smy = py, smz = pz;
    #pragma unroll
    for (int off = 1; off < 32; off <<= 1) {
        float t;
        t = __shfl_up_sync(0xffffffffu, pmy, off);  if (lane >= off) pmy = fmaxf(pmy, t);
        t = __shfl_up_sync(0xffffffffu, pmz, off);  if (lane >= off) pmz = fmaxf(pmz, t);
        t = __shfl_down_sync(0xffffffffu, smy, off); if (lane + off < 32) smy = fmaxf(smy, t);
        t = __shfl_down_sync(0xffffffffu, smz, off); if (lane + off < 32) smz = fmaxf(smz, t);
    }
    list[lane] = make_float4(__int_as_float(key), py, pz, 0.f);
    if (isD) {
        g_dpm[e * 32 + lane] = make_float2(pmy, pmz);
        g_dsm[e * 32 + lane] = make_float2(smy, smz);
    }
}

// ---------------- K2: windowed pairwise max + fused softmax ----------------------
__global__ __launch_bounds__(256) void k_pair(const float* __restrict__ bs,
                                              float* __restrict__ out) {
    __shared__ float2 s_emb[MAXD];
    __shared__ int    s_ds[16][32];
    __shared__ float2 s_yz[16][32];
    __shared__ float2 s_pm[16][32];
    __shared__ float2 s_sm[16][32];
    int ce = blockIdx.x;
    int dg = blockIdx.y;
    int tid = threadIdx.x;
    for (int i = tid; i < MAXD; i += 256) s_emb[i] = g_emb[i];
    for (int i = tid; i < 16 * 32; i += 256) {
        int dd = i >> 5, slot = i & 31;
        int de = dg * 16 + dd;
        float4 r = g_dlist[de * CAP + slot];
        s_ds[dd][slot] = __float_as_int(r.x);
        s_yz[dd][slot] = make_float2(r.y, r.z);
        s_pm[dd][slot] = g_dpm[de * 32 + slot];
        s_sm[dd][slot] = g_dsm[de * 32 + slot];
    }
    __syncthreads();

    int lane = tid & 31, w = tid >> 5;
    int nc = min(g_cnt[ce], CAP);
    float2 e599 = s_emb[MAXD - 1];
    float bs0 = __ldg(&bs[0]), bs1 = __ldg(&bs[1]);

    float M0[2] = {-INFINITY, -INFINITY};
    float M1[2] = {-INFINITY, -INFINITY};

    for (int c0 = 0; c0 < nc; c0 += 32) {
        int ci = c0 + lane;
        float4 cr = (ci < nc) ? g_clist[ce * CAP + ci]
                              : make_float4(0.f, -INFINITY, -INFINITY, 0.f);
        int cs = __float_as_int(cr.x);
        int t1 = cs - 598, tgt2 = cs + 599;

        #pragma unroll
        for (int dit = 0; dit < 2; dit++) {
            int dd = dit * 8 + w;
            int lo = 0, hi = 0;
            #pragma unroll
            for (int s = 16; s > 0; s >>= 1) {
                if (s_ds[dd][lo + s - 1] < t1)   lo += s;
                if (s_ds[dd][hi + s - 1] < tgt2) hi += s;
            }
            if (lo < 32 && s_ds[dd][lo] < t1)   lo += 1;
            if (hi < 32 && s_ds[dd][hi] < tgt2) hi += 1;
            float lpx = (lo > 0)  ? s_pm[dd][lo - 1].x : -INFINITY;
            float lpy = (lo > 0)  ? s_pm[dd][lo - 1].y : -INFINITY;
            float rsx = (hi < 32) ? s_sm[dd][hi].x     : -INFINITY;
            float rsy = (hi < 32) ? s_sm[dd][hi].y     : -INFINITY;
            float mmx = fmaxf(lpx, rsx) + e599.x;
            float mmy = fmaxf(lpy, rsy) + e599.y;
            for (int j = lo; j < hi; j++) {
                int dsj = s_ds[dd][j];
                float2 yz = s_yz[dd][j];
                int d = abs(cs - dsj);
                float2 ev = s_emb[d];
                mmx = fmaxf(mmx, yz.x + ev.x);
                mmy = fmaxf(mmy, yz.y + ev.y);
            }
            int de = dg * 16 + dd;
            int nd = min(g_cnt[NENT + de], CAP);
            for (int j = 32; j < nd; j++) {
                float4 dr = g_dlist[de * CAP + j];
                int d = min(__usad((unsigned)cs, (unsigned)__float_as_int(dr.x), 0u),
                            (unsigned)(MAXD - 1));
                float2 ev = s_emb[d];
                mmx = fmaxf(mmx, dr.y + ev.x);
                mmy = fmaxf(mmy, dr.z + ev.y);
            }
            M0[dit] = fmaxf(M0[dit], cr.y + mmx);
            M1[dit] = fmaxf(M1[dit], cr.z + mmy);
        }
    }

    #pragma unroll
    for (int dit = 0; dit < 2; dit++) {
        float m0 = M0[dit], m1 = M1[dit];
        #pragma unroll
        for (int off = 16; off > 0; off >>= 1) {
            m0 = fmaxf(m0, __shfl_xor_sync(0xffffffffu, m0, off));
            m1 = fmaxf(m1, __shfl_xor_sync(0xffffffffu, m1, off));
        }
        if (lane == 0) {
            int de = dg * 16 + dit * 8 + w;
            float x0 = m0 + bs0, x1 = m1 + bs1;
            float mx = fmaxf(x0, x1);
            float e0 = expf(x0 - mx), e1 = expf(x1 - mx);
            float inv = 1.f / (e0 + e1);
            out[(ce * NENT + de) * 2 + 0] = e0 * inv;
            out[(ce * NENT + de) * 2 + 1] = e1 * inv;
        }
    }

    __threadfence();
    __syncthreads();
    if (tid == 0) {
        int old = atomicAdd(&g_done, 1);
        if (old == NENT * 8 - 1) {
            #pragma unroll 1
            for (int i = 0; i < 2 * NENT; i++) g_cnt[i] = 0;
            g_done = 0;
            __threadfence();
        }
    }
}

// ---------------- launch ----------------
extern "C" void kernel_launch(void* const* d_in, const int* in_sizes, int n_in,
                              void* d_out, int out_size) {
    const float* h    = (const float*)d_in[0];
    const void*  csp  = d_in[1];
    const void*  cent = d_in[2];
    const void*  dsp  = d_in[3];
    const void*  dent = d_in[4];
    const float* Wc   = (const float*)d_in[5];
    const float* bc   = (const float*)d_in[6];
    const float* Wd   = (const float*)d_in[7];
    const float* bd   = (const float*)d_in[8];
    const float* Wemb = (const float*)d_in[9];
    const float* Ws   = (const float*)d_in[10];
    const float* bs   = (const float*)d_in[11];
    float* out = (float*)d_out;

    k_mention<<<2 * MM / BMM, NTH>>>(h, csp, cent, dsp, dent, Wc, bc, Wd, bd, Ws, Wemb);
    k_sort<<<32, 256>>>();
    k_pair<<<dim3(NENT, 8), 256>>>(bs, out);
}

// round 15
// speedup vs baseline: 1.1276x; 1.0520x over previous
#include <cuda_runtime.h>
#include <math.h>

#define TT    8192
#define HH    512
#define MM    4096
#define NENT  128
#define MAXD  600
#define NF    100
#define CAP   512

// ---------------- scratch ----------------
__device__ float2 g_emb[MAXD];
__device__ int    g_cnt[2 * NENT];      // zero at load; re-zeroed by k_pair tail
__device__ int    g_done;
__device__ float4 g_clist[NENT * CAP];  // (start_bits, sc0, sc1, 0)
__device__ float4 g_dlist[NENT * CAP];

__device__ __forceinline__ int ldI(const void* p, int idx, int is64) {
    return is64 ? (int)((const long long*)p)[idx] : ((const int*)p)[idx];
}
__device__ __forceinline__ void fma2(unsigned long long& d, unsigned long long a,
                                     unsigned long long b) {
    asm("fma.rn.f32x2 %0, %1, %2, %0;" : "+l"(d) : "l"(a), "l"(b));
}
__device__ __forceinline__ void upk2(unsigned long long v, float& lo, float& hi) {
    asm("mov.b64 {%0, %1}, %2;" : "=f"(lo), "=f"(hi) : "l"(v));
}
__device__ __forceinline__ float tanh_fast(float x) {
    float y;
    asm("tanh.approx.f32 %0, %1;" : "=f"(y) : "f"(x));
    return y;
}

// ---------------- K1: fused span-sum + GEMM + tanh + Ws dot + bin ----------------
// 128 blocks (BMM=64), 320 threads. kh = tid/160 (k half), t2 = tid%160,
// rg = t2%16 -> rows rg+16i (i<4), cg = t2/16 (0..9) -> col pairs p = cg+10j.
// Inner loop software-pipelined: kk+1's 9 LDS prefetched under kk's 20 FFMA2.
#define BMM  64
#define BKK  32
#define NTH  320
#define ADP  130
#define WPAD 104
#define AS_F (BKK * ADP)
#define WT_F (BKK * WPAD)
#define EPI_F (64 * 50 * 2 + 64 * 10 * 2)
#define POOLF (AS_F + WT_F > EPI_F ? AS_F + WT_F : EPI_F)

__global__ __launch_bounds__(NTH, 1) void k_mention(
        const float* __restrict__ h,
        const void* __restrict__ csp, const void* __restrict__ cent,
        const void* __restrict__ dsp, const void* __restrict__ dent,
        const float* __restrict__ Wc, const float* __restrict__ bc,
        const float* __restrict__ Wd, const float* __restrict__ bd,
        const float* __restrict__ Ws,
        const float* __restrict__ Wemb) {
    __shared__ __align__(16) float pool[POOLF];
    __shared__ int ss[BMM], se[BMM], sent[BMM];
    __shared__ int s_is64;

    float* Asd = pool;
    float* Wt  = pool + AS_F;

    int tid = threadIdx.x;
    int m0 = blockIdx.x * BMM;
    bool isC = (m0 < MM);
    const float* W  = isC ? Wc : Wd;
    const float* bb = isC ? bc : bd;
    int wsb = isC ? 0 : NF;

    if (tid < 32) {
        unsigned v = (unsigned)((const int*)csp)[1 + 2 * tid];
        unsigned any = __ballot_sync(0xffffffffu, v != 0u);
        if (tid == 0) s_is64 = (any == 0u) ? 1 : 0;
    }
    __syncthreads();
    int is64 = s_is64;
    if (tid < BMM) {
        int mi = (m0 + tid) - (isC ? 0 : MM);
        const void* sp = isC ? csp : dsp;
        const void* en = isC ? cent : dent;
        ss[tid]   = ldI(sp, 2 * mi, is64);
        se[tid]   = ldI(sp, 2 * mi + 1, is64);
        sent[tid] = ldI(en, mi, is64);
    }
    __syncthreads();

    int kh = tid / 160;
    int t2 = tid - kh * 160;
    int rg = t2 & 15;
    int cg = t2 >> 4;
    int kh16 = kh * 16;

    const float4* __restrict__ hp = (const float4*)h;
    int r0 = tid >> 3, q0 = tid & 7;
    int n0 = se[r0] - ss[r0];
    const float4* p0 = hp + (size_t)ss[r0] * (HH / 4) + q0;
    int i1 = tid + NTH;
    bool has1 = (i1 < BMM * 8);
    int r1 = has1 ? (i1 >> 3) : 0, q1 = has1 ? (i1 & 7) : 0;
    int n1 = se[r1] - ss[r1];
    const float4* p1 = hp + (size_t)ss[r1] * (HH / 4) + q1;

    int kkp[5], c2p[5];
    #pragma unroll
    for (int p = 0; p < 5; p++) {
        int i = tid + NTH * p;
        kkp[p] = i / 50;
        c2p[p] = i - kkp[p] * 50;
    }

    unsigned long long acc[4][5];
    #pragma unroll
    for (int i = 0; i < 4; i++)
        #pragma unroll
        for (int j = 0; j < 5; j++) acc[i][j] = 0ull;

    float4 v0[8], v1[8];
    float2 wr[5];

    #pragma unroll
    for (int t = 0; t < 8; t++) v0[t] = __ldg(p0 + (size_t)min(t, n0) * (HH / 4));
    if (has1) {
        #pragma unroll
        for (int t = 0; t < 8; t++) v1[t] = __ldg(p1 + (size_t)min(t, n1) * (HH / 4));
    }
    #pragma unroll
    for (int p = 0; p < 5; p++)
        wr[p] = __ldg((const float2*)&W[(size_t)kkp[p] * NF + 2 * c2p[p]]);

    for (int tile = 0; tile < HH / BKK; tile++) {
        // ---- commit prefetched regs -> smem (duplicated A) ----
        {
            float4 a = v0[0];
            #pragma unroll
            for (int t = 1; t < 8; t++)
                if (t <= n0) { a.x += v0[t].x; a.y += v0[t].y; a.z += v0[t].z; a.w += v0[t].w; }
            *(float2*)&Asd[(4 * q0 + 0) * ADP + 2 * r0] = make_float2(a.x, a.x);
            *(float2*)&Asd[(4 * q0 + 1) * ADP + 2 * r0] = make_float2(a.y, a.y);
            *(float2*)&Asd[(4 * q0 + 2) * ADP + 2 * r0] = make_float2(a.z, a.z);
            *(float2*)&Asd[(4 * q0 + 3) * ADP + 2 * r0] = make_float2(a.w, a.w);
            if (has1) {
                float4 b = v1[0];
                #pragma unroll
                for (int t = 1; t < 8; t++)
                    if (t <= n1) { b.x += v1[t].x; b.y += v1[t].y; b.z += v1[t].z; b.w += v1[t].w; }
                *(float2*)&Asd[(4 * q1 + 0) * ADP + 2 * r1] = make_float2(b.x, b.x);
                *(float2*)&Asd[(4 * q1 + 1) * ADP + 2 * r1] = make_float2(b.y, b.y);
                *(float2*)&Asd[(4 * q1 + 2) * ADP + 2 * r1] = make_float2(b.z, b.z);
                *(float2*)&Asd[(4 * q1 + 3) * ADP + 2 * r1] = make_float2(b.w, b.w);
            }
            #pragma unroll
            for (int p = 0; p < 5; p++)
                *(float2*)&Wt[kkp[p] * WPAD + 2 * c2p[p]] = wr[p];
        }
        __syncthreads();
        // ---- issue next tile's global loads ----
        if (tile + 1 < HH / BKK) {
            int off = (tile + 1) * (BKK / 4);
            v0[0] = __ldg(p0 + off);
            #pragma unroll
            for (int t = 1; t < 8; t++)
                if (t <= n0) v0[t] = __ldg(p0 + off + (size_t)t * (HH / 4));
            if (has1) {
                v1[0] = __ldg(p1 + off);
                #pragma unroll
                for (int t = 1; t < 8; t++)
                    if (t <= n1) v1[t] = __ldg(p1 + off + (size_t)t * (HH / 4));
            }
            int kb = (tile + 1) * BKK * NF;
            #pragma unroll
            for (int p = 0; p < 5; p++)
                wr[p] = __ldg((const float2*)&W[kb + (size_t)kkp[p] * NF + 2 * c2p[p]]);
        }
        // ---- compute: software-pipelined (LDS of kk+1 under FFMA2 of kk) ----
        {
            const float* ab = &Asd[kh16 * ADP + 2 * rg];
            const float* wb = &Wt[kh16 * WPAD + 2 * cg];
            unsigned long long ca0 = *(const unsigned long long*)(ab);
            unsigned long long ca1 = *(const unsigned long long*)(ab + 32);
            unsigned long long ca2 = *(const unsigned long long*)(ab + 64);
            unsigned long long ca3 = *(const unsigned long long*)(ab + 96);
            unsigned long long cw0 = *(const unsigned long long*)(wb);
            unsigned long long cw1 = *(const unsigned long long*)(wb + 20);
            unsigned long long cw2 = *(const unsigned long long*)(wb + 40);
            unsigned long long cw3 = *(const unsigned long long*)(wb + 60);
            unsigned long long cw4 = *(const unsigned long long*)(wb + 80);
            #pragma unroll
            for (int kki = 0; kki < 16; kki++) {
                unsigned long long na0 = 0, na1 = 0, na2 = 0, na3 = 0;
                unsigned long long nw0 = 0, nw1 = 0, nw2 = 0, nw3 = 0, nw4 = 0;
                if (kki < 15) {
                    const float* ab2 = &Asd[(kh16 + kki + 1) * ADP + 2 * rg];
                    const float* wb2 = &Wt[(kh16 + kki + 1) * WPAD + 2 * cg];
                    na0 = *(const unsigned long long*)(ab2);
                    na1 = *(const unsigned long long*)(ab2 + 32);
                    na2 = *(const unsigned long long*)(ab2 + 64);
                    na3 = *(const unsigned long long*)(ab2 + 96);
                    nw0 = *(const unsigned long long*)(wb2);
                    nw1 = *(const unsigned long long*)(wb2 + 20);
                    nw2 = *(const unsigned long long*)(wb2 + 40);
                    nw3 = *(const unsigned long long*)(wb2 + 60);
                    nw4 = *(const unsigned long long*)(wb2 + 80);
                }
                fma2(acc[0][0], ca0, cw0); fma2(acc[1][0], ca1, cw0);
                fma2(acc[2][0], ca2, cw0); fma2(acc[3][0], ca3, cw0);
                fma2(acc[0][1], ca0, cw1); fma2(acc[1][1], ca1, cw1);
                fma2(acc[2][1], ca2, cw1); fma2(acc[3][1], ca3, cw1);
                fma2(acc[0][2], ca0, cw2); fma2(acc[1][2], ca1, cw2);
                fma2(acc[2][2], ca2, cw2); fma2(acc[3][2], ca3, cw2);
                fma2(acc[0][3], ca0, cw3); fma2(acc[1][3], ca1, cw3);
                fma2(acc[2][3], ca2, cw3); fma2(acc[3][3], ca3, cw3);
                fma2(acc[0][4], ca0, cw4); fma2(acc[1][4], ca1, cw4);
                fma2(acc[2][4], ca2, cw4); fma2(acc[3][4], ca3, cw4);
                ca0 = na0; ca1 = na1; ca2 = na2; ca3 = na3;
                cw0 = nw0; cw1 = nw1; cw2 = nw2; cw3 = nw3; cw4 = nw4;
            }
        }
        __syncthreads();   // WAR: next commit overwrites Asd/Wt
    }

    // ---- merge k-halves + epilogue (alias pool) ----
    float2* red  = (float2*)pool;
    float*  red2 = pool + 2 * 64 * 50;

    if (kh == 0) {
        #pragma unroll
        for (int i = 0; i < 4; i++)
            #pragma unroll
            for (int j = 0; j < 5; j++) {
                float lo, hi;
                upk2(acc[i][j], lo, hi);
                red[(rg + 16 * i) * 50 + (cg + 10 * j)] = make_float2(lo, hi);
            }
    }
    __syncthreads();
    if (kh == 1) {
        float s0[4] = {0.f, 0.f, 0.f, 0.f}, s1[4] = {0.f, 0.f, 0.f, 0.f};
        #pragma unroll
        for (int j = 0; j < 5; j++) {
            int p = cg + 10 * j, c0 = 2 * p;
            float2 bias = *(const float2*)&bb[c0];
            float2 w0 = *(const float2*)&Ws[(wsb + c0) * 2];
            float2 w1 = *(const float2*)&Ws[(wsb + c0 + 1) * 2];
            #pragma unroll
            for (int i = 0; i < 4; i++) {
                float lo, hi;
                upk2(acc[i][j], lo, hi);
                float2 o = red[(rg + 16 * i) * 50 + p];
                float t0 = tanh_fast(lo + o.x + bias.x);
                float t1 = tanh_fast(hi + o.y + bias.y);
                s0[i] += t0 * w0.x + t1 * w1.x;
                s1[i] += t0 * w0.y + t1 * w1.y;
            }
        }
        #pragma unroll
        for (int i = 0; i < 4; i++) {
            int r = rg + 16 * i;
            red2[(r * 10 + cg) * 2 + 0] = s0[i];
            red2[(r * 10 + cg) * 2 + 1] = s1[i];
        }
    }
    __syncthreads();
    if (tid < BMM) {
        float s0 = 0.f, s1 = 0.f;
        #pragma unroll
        for (int c = 0; c < 10; c++) {
            s0 += red2[(tid * 10 + c) * 2 + 0];
            s1 += red2[(tid * 10 + c) * 2 + 1];
        }
        int ent = sent[tid];
        int pos = atomicAdd(&g_cnt[(isC ? 0 : NENT) + ent], 1);
        if (pos < CAP) {
            float4 rec;
            rec.x = __int_as_float(ss[tid]);
            rec.y = s0; rec.z = s1; rec.w = 0.f;
            (isC ? g_clist : g_dlist)[ent * CAP + pos] = rec;
        }
    }

    if (blockIdx.x < 8) {
        for (int i = tid; i < 75 * 2; i += NTH) {
            int d = 75 * blockIdx.x + (i >> 1), k = i & 1;
            float a = 0.f;
            #pragma unroll
            for (int j = 0; j < 50; j++)
                a += Wemb[d * 50 + j] * Ws[(200 + j) * 2 + k];
            if (k == 0) g_emb[d].x = a; else g_emb[d].y = a;
        }
    }
}

// ---------------- K2: inline dis-bin sort + windowed pairwise max + softmax -------
__global__ __launch_bounds__(256) void k_pair(const float* __restrict__ bs,
                                              float* __restrict__ out) {
    __shared__ float2 s_emb[MAXD];
    __shared__ int    s_ds[16][32];
    __shared__ float2 s_yz[16][32];
    __shared__ float2 s_pm[16][32];
    __shared__ float2 s_sm[16][32];
    int ce = blockIdx.x;
    int dg = blockIdx.y;
    int tid = threadIdx.x;
    int lane = tid & 31, w = tid >> 5;
    for (int i = tid; i < MAXD; i += 256) s_emb[i] = g_emb[i];

    // inline per-bin bitonic sort + prefix/suffix max (warp w: bins w, 8+w)
    #pragma unroll
    for (int b2 = 0; b2 < 2; b2++) {
        int dd = b2 * 8 + w;
        int de = dg * 16 + dd;
        int n = min(g_cnt[NENT + de], 32);
        int key = 0x7FFFFFFF;
        float py = -INFINITY, pz = -INFINITY;
        if (lane < n) {
            float4 r = g_dlist[de * CAP + lane];
            key = __float_as_int(r.x);
            py = r.y; pz = r.z;
        }
        #pragma unroll
        for (int k = 2; k <= 32; k <<= 1) {
            #pragma unroll
            for (int j = k >> 1; j > 0; j >>= 1) {
                int   ok = __shfl_xor_sync(0xffffffffu, key, j);
                float oy = __shfl_xor_sync(0xffffffffu, py, j);
                float oz = __shfl_xor_sync(0xffffffffu, pz, j);
                bool up = ((lane & k) == 0);
                bool lower = ((lane & j) == 0);
                bool takeMin = (lower == up);
                bool takeOther = takeMin ? (ok < key) : (ok > key);
                if (takeOther) { key = ok; py = oy; pz = oz; }
            }
        }
        float pmy = py, pmz = pz, smy = py, smz = pz;
        #pragma unroll
        for (int off = 1; off < 32; off <<= 1) {
            float t;
            t = __shfl_up_sync(0xffffffffu, pmy, off);   if (lane >= off) pmy = fmaxf(pmy, t);
            t = __shfl_up_sync(0xffffffffu, pmz, off);   if (lane >= off) pmz = fmaxf(pmz, t);
            t = __shfl_down_sync(0xffffffffu, smy, off); if (lane + off < 32) smy = fmaxf(smy, t);
            t = __shfl_down_sync(0xffffffffu, smz, off); if (lane + off < 32) smz = fmaxf(smz, t);
        }
        s_ds[dd][lane] = key;
        s_yz[dd][lane] = make_float2(py, pz);
        s_pm[dd][lane] = make_float2(pmy, pmz);
        s_sm[dd][lane] = make_float2(smy, smz);
    }
    __syncthreads();

    int nc = min(g_cnt[ce], CAP);
    float2 e599 = s_emb[MAXD - 1];
    float bs0 = __ldg(&bs[0]), bs1 = __ldg(&bs[1]);

    float M0[2] = {-INFINITY, -INFINITY};
    float M1[2] = {-INFINITY, -INFINITY};

    for (int c0 = 0; c0 < nc; c0 += 32) {
        int ci = c0 + lane;
        float4 cr = (ci < nc) ? g_clist[ce * CAP + ci]
                              : make_float4(0.f, -INFINITY, -INFINITY, 0.f);
        int cs = __float_as_int(cr.x);
        int t1 = cs - 598, tgt2 = cs + 599;

        #pragma unroll
        for (int dit = 0; dit < 2; dit++) {
            int dd = dit * 8 + w;
            int lo = 0, hi = 0;
            #pragma unroll
            for (int s = 16; s > 0; s >>= 1) {
                if (s_ds[dd][lo + s - 1] < t1)   lo += s;
                if (s_ds[dd][hi + s - 1] < tgt2) hi += s;
            }
            if (lo < 32 && s_ds[dd][lo] < t1)   lo += 1;
            if (hi < 32 && s_ds[dd][hi] < tgt2) hi += 1;
            float lpx = (lo > 0)  ? s_pm[dd][lo - 1].x : -INFINITY;
            float lpy = (lo > 0)  ? s_pm[dd][lo - 1].y : -INFINITY;
            float rsx = (hi < 32) ? s_sm[dd][hi].x     : -INFINITY;
            float rsy = (hi < 32) ? s_sm[dd][hi].y     : -INFINITY;
            float mmx = fmaxf(lpx, rsx) + e599.x;
            float mmy = fmaxf(lpy, rsy) + e599.y;
            for (int j = lo; j < hi; j++) {
                int dsj = s_ds[dd][j];
                float2 yz = s_yz[dd][j];
                int d = abs(cs - dsj);
                float2 ev = s_emb[d];
                mmx = fmaxf(mmx, yz.x + ev.x);
                mmy = fmaxf(mmy, yz.y + ev.y);
            }
            int de = dg * 16 + dd;
            int nd = min(g_cnt[NENT + de], CAP);
            for (int j = 32; j < nd; j++) {
                float4 dr = g_dlist[de * CAP + j];
                int d = min(__usad((unsigned)cs, (unsigned)__float_as_int(dr.x), 0u),
                            (unsigned)(MAXD - 1));
                float2 ev = s_emb[d];
                mmx = fmaxf(mmx, dr.y + ev.x);
                mmy = fmaxf(mmy, dr.z + ev.y);
            }
            M0[dit] = fmaxf(M0[dit], cr.y + mmx);
            M1[dit] = fmaxf(M1[dit], cr.z + mmy);
        }
    }

    #pragma unroll
    for (int dit = 0; dit < 2; dit++) {
        float m0 = M0[dit], m1 = M1[dit];
        #pragma unroll
        for (int off = 16; off > 0; off >>= 1) {
            m0 = fmaxf(m0, __shfl_xor_sync(0xffffffffu, m0, off));
            m1 = fmaxf(m1, __shfl_xor_sync(0xffffffffu, m1, off));
        }
        if (lane == 0) {
            int de = dg * 16 + dit * 8 + w;
            float x0 = m0 + bs0, x1 = m1 + bs1;
            float mx = fmaxf(x0, x1);
            float e0 = expf(x0 - mx), e1 = expf(x1 - mx);
            float inv = 1.f / (e0 + e1);
            out[(ce * NENT + de) * 2 + 0] = e0 * inv;
            out[(ce * NENT + de) * 2 + 1] = e1 * inv;
        }
    }

    // ticket: last block re-zeroes g_cnt (+g_done) for next replay
    __threadfence();
    __syncthreads();
    if (tid == 0) {
        int old = atomicAdd(&g_done, 1);
        if (old == NENT * 8 - 1) {
            #pragma unroll 1
            for (int i = 0; i < 2 * NENT; i++) g_cnt[i] = 0;
            g_done = 0;
            __threadfence();
        }
    }
}

// ---------------- launch ----------------
extern "C" void kernel_launch(void* const* d_in, const int* in_sizes, int n_in,
                              void* d_out, int out_size) {
    const float* h    = (const float*)d_in[0];
    const void*  csp  = d_in[1];
    const void*  cent = d_in[2];
    const void*  dsp  = d_in[3];
    const void*  dent = d_in[4];
    const float* Wc   = (const float*)d_in[5];
    const float* bc   = (const float*)d_in[6];
    const float* Wd   = (const float*)d_in[7];
    const float* bd   = (const float*)d_in[8];
    const float* Wemb = (const float*)d_in[9];
    const float* Ws   = (const float*)d_in[10];
    const float* bs   = (const float*)d_in[11];
    float* out = (float*)d_out;

    k_mention<<<2 * MM / BMM, NTH>>>(h, csp, cent, dsp, dent, Wc, bc, Wd, bd, Ws, Wemb);
    k_pair<<<dim3(NENT, 8), 256>>>(bs, out);
}

// round 17
// speedup vs baseline: 1.3055x; 1.1578x over previous
#include <cuda_runtime.h>
#include <cuda_bf16.h>
#include <mma.h>
#include <math.h>

using namespace nvcuda;

#define TT    8192
#define HH    512
#define MM    4096
#define NENT  128
#define MAXD  600
#define NF    100
#define CAP   512

#define NBP   112              // padded N for bf16 W (7 n16 tiles)
#define BMM   64               // mentions per block
#define BKK   32               // k per tile
#define NT16  (HH / BKK)       // 16 tiles

// ---------------- scratch ----------------
__device__ float2 g_emb[MAXD];
__device__ int    g_cnt[2 * NENT];
__device__ int    g_done;
__device__ float4 g_clist[NENT * CAP];
__device__ float4 g_dlist[NENT * CAP];
__device__ __nv_bfloat16 g_wbh[2 * HH * NBP];   // W split hi (chem|dis), [k][n]
__device__ __nv_bfloat16 g_wbl[2 * HH * NBP];   // W split lo

__device__ __forceinline__ int ldI(const void* p, int idx, int is64) {
    return is64 ? (int)((const long long*)p)[idx] : ((const int*)p)[idx];
}
__device__ __forceinline__ float tanh_fast(float x) {
    float y;
    asm("tanh.approx.f32 %0, %1;" : "=f"(y) : "f"(x));
    return y;
}

// ---------------- K0: split W into bf16 hi/lo, padded to 112 cols ----------------
__global__ void k_prep(const float* __restrict__ Wc, const float* __restrict__ Wd) {
    int idx = blockIdx.x * 256 + threadIdx.x;
    if (idx >= 2 * HH * NBP) return;
    int ty = idx / (HH * NBP);
    int rem = idx - ty * HH * NBP;
    int k = rem / NBP;
    int n = rem - k * NBP;
    const float* W = ty ? Wd : Wc;
    float v = (n < NF) ? __ldg(&W[k * NF + n]) : 0.f;
    __nv_bfloat16 h = __float2bfloat16(v);
    float r = v - __bfloat162float(h);
    g_wbh[idx] = h;
    g_wbl[idx] = __float2bfloat16(r);
}

// ---------------- K1: fused span-sum + bf16x3 wmma GEMM + tanh + Ws dot + bin -----
// 128 blocks x 256 threads (8 warps). Warp (wm = w&3, wn = w>>2):
// m-strip rows 16wm..16wm+15; n16 tiles jt in {0..3} (wn=0) or {4..6} (wn=1).
// smem: Ahi/Alo bf16[64][40], Bsh/Bsl bf16[32][120]; epilogue alias Ds f32[64][116].
#define ALD   40
#define BLD   120
#define DLD   116
#define AH_B  0
#define AL_B  (64 * ALD * 2)                 // 5120
#define BH_B  (2 * 64 * ALD * 2)             // 10240
#define BL_B  (BH_B + 32 * BLD * 2)          // 17920
#define DS_B  0
#define RED_B (64 * DLD * 4)                 // 29696
#define POOLB (RED_B + 64 * 4 * 2 * 4)       // 31744 bytes

__global__ __launch_bounds__(256, 1) void k_mention(
        const float* __restrict__ h,
        const void* __restrict__ csp, const void* __restrict__ cent,
        const void* __restrict__ dsp, const void* __restrict__ dent,
        const float* __restrict__ bc, const float* __restrict__ bd,
        const float* __restrict__ Ws,
        const float* __restrict__ Wemb) {
    __shared__ __align__(32) char pool[POOLB];
    __shared__ int ss[BMM], se[BMM], sent[BMM];
    __shared__ float s_bias[NF], s_w0[NF], s_w1[NF];
    __shared__ int s_is64;

    __nv_bfloat16* Ahi = (__nv_bfloat16*)(pool + AH_B);
    __nv_bfloat16* Alo = (__nv_bfloat16*)(pool + AL_B);
    __nv_bfloat16* Bsh = (__nv_bfloat16*)(pool + BH_B);
    __nv_bfloat16* Bsl = (__nv_bfloat16*)(pool + BL_B);

    int tid = threadIdx.x;
    int wid = tid >> 5;
    int m0 = blockIdx.x * BMM;
    bool isC = (m0 < MM);
    const float* bb = isC ? bc : bd;
    int wsb = isC ? 0 : NF;

    if (tid < 32) {
        unsigned v = (unsigned)((const int*)csp)[1 + 2 * tid];
        unsigned any = __ballot_sync(0xffffffffu, v != 0u);
        if (tid == 0) s_is64 = (any == 0u) ? 1 : 0;
    }
    __syncthreads();
    int is64 = s_is64;
    if (tid < BMM) {
        int mi = (m0 + tid) - (isC ? 0 : MM);
        const void* sp = isC ? csp : dsp;
        const void* en = isC ? cent : dent;
        ss[tid]   = ldI(sp, 2 * mi, is64);
        se[tid]   = ldI(sp, 2 * mi + 1, is64);
        sent[tid] = ldI(en, mi, is64);
    }
    for (int i = tid; i < NF; i += 256) {
        s_bias[i] = bb[i];
        float2 w = *(const float2*)&Ws[(wsb + i) * 2];
        s_w0[i] = w.x;
        s_w1[i] = w.y;
    }
    __syncthreads();

    // ---- A span tasks: 512 tasks (64 rows x 8 q), 2 per thread ----
    const float4* __restrict__ hp = (const float4*)h;
    int r0 = tid >> 3, q0 = tid & 7;                 // rows 0..31
    int n0 = se[r0] - ss[r0];
    const float4* p0 = hp + (size_t)ss[r0] * (HH / 4) + q0;
    int r1 = r0 + 32;                                 // rows 32..63
    int n1 = se[r1] - ss[r1];
    const float4* p1 = hp + (size_t)ss[r1] * (HH / 4) + q0;

    // ---- B copy tasks: 896 uint4 (hi 448 | lo 448), up to 4 per thread ----
    const __nv_bfloat16* wbh = g_wbh + (isC ? 0 : HH * NBP);
    const __nv_bfloat16* wbl = g_wbl + (isC ? 0 : HH * NBP);
    int brow[4], bc4[4];
    bool bm[4], bv[4];
    #pragma unroll
    for (int p = 0; p < 4; p++) {
        int i = tid + 256 * p;
        bv[p] = (i < 896);
        int ii = bv[p] ? i : 0;
        bm[p] = (ii >= 448);
        int j = ii - (bm[p] ? 448 : 0);
        brow[p] = j / 14;
        bc4[p] = j - brow[p] * 14;
    }

    wmma::fragment<wmma::accumulator, 16, 16, 16, float> dfr[4];
    int wm = wid & 3, wn = wid >> 2;
    int NTJ = wn ? 3 : 4;
    int jb = wn ? 4 : 0;
    #pragma unroll
    for (int j = 0; j < 4; j++) wmma::fill_fragment(dfr[j], 0.f);

    float4 v0[8], v1[8];
    uint4 bq[4];

    // prologue: tile-0 loads
    #pragma unroll
    for (int t = 0; t < 8; t++) v0[t] = __ldg(p0 + (size_t)min(t, n0) * (HH / 4));
    #pragma unroll
    for (int t = 0; t < 8; t++) v1[t] = __ldg(p1 + (size_t)min(t, n1) * (HH / 4));
    #pragma unroll
    for (int p = 0; p < 4; p++)
        if (bv[p]) {
            const __nv_bfloat16* src = (bm[p] ? wbl : wbh) + (size_t)brow[p] * NBP + 8 * bc4[p];
            bq[p] = *(const uint4*)src;
        }

    for (int t = 0; t < NT16; t++) {
        // ---- commit A (bf16 split) + B ----
        {
            float4 a = v0[0];
            #pragma unroll
            for (int tt = 1; tt < 8; tt++)
                if (tt <= n0) { a.x += v0[tt].x; a.y += v0[tt].y; a.z += v0[tt].z; a.w += v0[tt].w; }
            __nv_bfloat162 h01 = __floats2bfloat162_rn(a.x, a.y);
            __nv_bfloat162 h23 = __floats2bfloat162_rn(a.z, a.w);
            __nv_bfloat162 l01 = __floats2bfloat162_rn(a.x - __low2float(h01), a.y - __high2float(h01));
            __nv_bfloat162 l23 = __floats2bfloat162_rn(a.z - __low2float(h23), a.w - __high2float(h23));
            *(uint2*)&Ahi[r0 * ALD + 4 * q0] = make_uint2(*(unsigned*)&h01, *(unsigned*)&h23);
            *(uint2*)&Alo[r0 * ALD + 4 * q0] = make_uint2(*(unsigned*)&l01, *(unsigned*)&l23);

            float4 b = v1[0];
            #pragma unroll
            for (int tt = 1; tt < 8; tt++)
                if (tt <= n1) { b.x += v1[tt].x; b.y += v1[tt].y; b.z += v1[tt].z; b.w += v1[tt].w; }
            h01 = __floats2bfloat162_rn(b.x, b.y);
            h23 = __floats2bfloat162_rn(b.z, b.w);
            l01 = __floats2bfloat162_rn(b.x - __low2float(h01), b.y - __high2float(h01));
            l23 = __floats2bfloat162_rn(b.z - __low2float(h23), b.w - __high2float(h23));
            *(uint2*)&Ahi[r1 * ALD + 4 * q0] = make_uint2(*(unsigned*)&h01, *(unsigned*)&h23);
            *(uint2*)&Alo[r1 * ALD + 4 * q0] = make_uint2(*(unsigned*)&l01, *(unsigned*)&l23);

            #pragma unroll
            for (int p = 0; p < 4; p++)
                if (bv[p]) {
                    __nv_bfloat16* dst = (bm[p] ? Bsl : Bsh) + brow[p] * BLD + 8 * bc4[p];
                    *(uint4*)dst = bq[p];
                }
        }
        __syncthreads();
        // ---- issue next tile's loads ----
        if (t + 1 < NT16) {
            int off = (t + 1) * (BKK / 4);
            v0[0] = __ldg(p0 + off);
            #pragma unroll
            for (int tt = 1; tt < 8; tt++)
                if (tt <= n0) v0[tt] = __ldg(p0 + off + (size_t)tt * (HH / 4));
            v1[0] = __ldg(p1 + off);
            #pragma unroll
            for (int tt = 1; tt < 8; tt++)
                if (tt <= n1) v1[tt] = __ldg(p1 + off + (size_t)tt * (HH / 4));
            size_t krow = (size_t)(t + 1) * BKK;
            #pragma unroll
            for (int p = 0; p < 4; p++)
                if (bv[p]) {
                    const __nv_bfloat16* src = (bm[p] ? wbl : wbh)
                        + (krow + brow[p]) * NBP + 8 * bc4[p];
                    bq[p] = *(const uint4*)src;
                }
        }
        // ---- compute: 2 k16 chunks x (A hi/lo frags + per n-tile 3 wmma) ----
        #pragma unroll
        for (int c = 0; c < 2; c++) {
            wmma::fragment<wmma::matrix_a, 16, 16, 16, __nv_bfloat16, wmma::row_major> fah, fal;
            wmma::load_matrix_sync(fah, Ahi + wm * 16 * ALD + c * 16, ALD);
            wmma::load_matrix_sync(fal, Alo + wm * 16 * ALD + c * 16, ALD);
            #pragma unroll
            for (int j = 0; j < 4; j++) {
                if (j >= NTJ) break;
                wmma::fragment<wmma::matrix_b, 16, 16, 16, __nv_bfloat16, wmma::row_major> fbh, fbl;
                const __nv_bfloat16* bp = Bsh + c * 16 * BLD + (jb + j) * 16;
                const __nv_bfloat16* bl = Bsl + c * 16 * BLD + (jb + j) * 16;
                wmma::load_matrix_sync(fbh, bp, BLD);
                wmma::load_matrix_sync(fbl, bl, BLD);
                wmma::mma_sync(dfr[j], fah, fbh, dfr[j]);
                wmma::mma_sync(dfr[j], fal, fbh, dfr[j]);
                wmma::mma_sync(dfr[j], fah, fbl, dfr[j]);
            }
        }
        __syncthreads();   // WAR: next commit overwrites tiles
    }

    // ---- epilogue: D -> smem, tanh + Ws dot, reduce, bin ----
    float* Ds   = (float*)(pool + DS_B);
    float* red2 = (float*)(pool + RED_B);
    #pragma unroll
    for (int j = 0; j < 4; j++) {
        if (j >= NTJ) break;
        wmma::store_matrix_sync(Ds + wm * 16 * DLD + (jb + j) * 16, dfr[j], DLD,
                                wmma::mem_row_major);
    }
    __syncthreads();
    {
        int row = tid & 63, qu = tid >> 6;
        int cbeg = 26 * qu;
        int cend = min(cbeg + 26, NF);
        float s0 = 0.f, s1 = 0.f;
        for (int cc = cbeg; cc < cend; cc++) {
            float x = Ds[row * DLD + cc] + s_bias[cc];
            float tv = tanh_fast(x);
            s0 += tv * s_w0[cc];
            s1 += tv * s_w1[cc];
        }
        red2[(row * 4 + qu) * 2 + 0] = s0;
        red2[(row * 4 + qu) * 2 + 1] = s1;
    }
    __syncthreads();
    if (tid < BMM) {
        float s0 = 0.f, s1 = 0.f;
        #pragma unroll
        for (int c = 0; c < 4; c++) {
            s0 += red2[(tid * 4 + c) * 2 + 0];
            s1 += red2[(tid * 4 + c) * 2 + 1];
        }
        int ent = sent[tid];
        int pos = atomicAdd(&g_cnt[(isC ? 0 : NENT) + ent], 1);
        if (pos < CAP) {
            float4 rec;
            rec.x = __int_as_float(ss[tid]);
            rec.y = s0; rec.z = s1; rec.w = 0.f;
            (isC ? g_clist : g_dlist)[ent * CAP + pos] = rec;
        }
    }

    // blocks 0..7: emb precontract (consumed only by k_pair)
    if (blockIdx.x < 8) {
        for (int i = tid; i < 75 * 2; i += 256) {
            int d = 75 * blockIdx.x + (i >> 1), k = i & 1;
            float a = 0.f;
            #pragma unroll
            for (int j = 0; j < 50; j++)
                a += Wemb[d * 50 + j] * Ws[(200 + j) * 2 + k];
            if (k == 0) g_emb[d].x = a; else g_emb[d].y = a;
        }
    }
}

// ---------------- K2: inline dis-bin sort + windowed pairwise max + softmax -------
__global__ __launch_bounds__(256) void k_pair(const float* __restrict__ bs,
                                              float* __restrict__ out) {
    __shared__ float2 s_emb[MAXD];
    __shared__ int    s_ds[16][32];
    __shared__ float2 s_yz[16][32];
    __shared__ float2 s_pm[16][32];
    __shared__ float2 s_sm[16][32];
    int ce = blockIdx.x;
    int dg = blockIdx.y;
    int tid = threadIdx.x;
    int lane = tid & 31, w = tid >> 5;
    for (int i = tid; i < MAXD; i += 256) s_emb[i] = g_emb[i];

    #pragma unroll
    for (int b2 = 0; b2 < 2; b2++) {
        int dd = b2 * 8 + w;
        int de = dg * 16 + dd;
        int n = min(g_cnt[NENT + de], 32);
        int key = 0x7FFFFFFF;
        float py = -INFINITY, pz = -INFINITY;
        if (lane < n) {
            float4 r = g_dlist[de * CAP + lane];
            key = __float_as_int(r.x);
            py = r.y; pz = r.z;
        }
        #pragma unroll
        for (int k = 2; k <= 32; k <<= 1) {
            #pragma unroll
            for (int j = k >> 1; j > 0; j >>= 1) {
                int   ok = __shfl_xor_sync(0xffffffffu, key, j);
                float oy = __shfl_xor_sync(0xffffffffu, py, j);
                float oz = __shfl_xor_sync(0xffffffffu, pz, j);
                bool up = ((lane & k) == 0);
                bool lower = ((lane & j) == 0);
                bool takeMin = (lower == up);
                bool takeOther = takeMin ? (ok < key) : (ok > key);
                if (takeOther) { key = ok; py = oy; pz = oz; }
            }
        }
        float pmy = py, pmz = pz, smy = py, smz = pz;
        #pragma unroll
        for (int off = 1; off < 32; off <<= 1) {
            float t;
            t = __shfl_up_sync(0xffffffffu, pmy, off);   if (lane >= off) pmy = fmaxf(pmy, t);
            t = __shfl_up_sync(0xffffffffu, pmz, off);   if (lane >= off) pmz = fmaxf(pmz, t);
            t = __shfl_down_sync(0xffffffffu, smy, off); if (lane + off < 32) smy = fmaxf(smy, t);
            t = __shfl_down_sync(0xffffffffu, smz, off); if (lane + off < 32) smz = fmaxf(smz, t);
        }
        s_ds[dd][lane] = key;
        s_yz[dd][lane] = make_float2(py, pz);
        s_pm[dd][lane] = make_float2(pmy, pmz);
        s_sm[dd][lane] = make_float2(smy, smz);
    }
    __syncthreads();

    int nc = min(g_cnt[ce], CAP);
    float2 e599 = s_emb[MAXD - 1];
    float bs0 = __ldg(&bs[0]), bs1 = __ldg(&bs[1]);

    float M0[2] = {-INFINITY, -INFINITY};
    float M1[2] = {-INFINITY, -INFINITY};

    for (int c0 = 0; c0 < nc; c0 += 32) {
        int ci = c0 + lane;
        float4 cr = (ci < nc) ? g_clist[ce * CAP + ci]
                              : make_float4(0.f, -INFINITY, -INFINITY, 0.f);
        int cs = __float_as_int(cr.x);
        int t1 = cs - 598, tgt2 = cs + 599;

        #pragma unroll
        for (int dit = 0; dit < 2; dit++) {
            int dd = dit * 8 + w;
            int lo = 0, hi = 0;
            #pragma unroll
            for (int s = 16; s > 0; s >>= 1) {
                if (s_ds[dd][lo + s - 1] < t1)   lo += s;
                if (s_ds[dd][hi + s - 1] < tgt2) hi += s;
            }
            if (lo < 32 && s_ds[dd][lo] < t1)   lo += 1;
            if (hi < 32 && s_ds[dd][hi] < tgt2) hi += 1;
            float lpx = (lo > 0)  ? s_pm[dd][lo - 1].x : -INFINITY;
            float lpy = (lo > 0)  ? s_pm[dd][lo - 1].y : -INFINITY;
            float rsx = (hi < 32) ? s_sm[dd][hi].x     : -INFINITY;
            float rsy = (hi < 32) ? s_sm[dd][hi].y     : -INFINITY;
            float mmx = fmaxf(lpx, rsx) + e599.x;
            float mmy = fmaxf(lpy, rsy) + e599.y;
            for (int j = lo; j < hi; j++) {
                int dsj = s_ds[dd][j];
                float2 yz = s_yz[dd][j];
                int d = abs(cs - dsj);
                float2 ev = s_emb[d];
                mmx = fmaxf(mmx, yz.x + ev.x);
                mmy = fmaxf(mmy, yz.y + ev.y);
            }
            int de = dg * 16 + dd;
            int nd = min(g_cnt[NENT + de], CAP);
            for (int j = 32; j < nd; j++) {
                float4 dr = g_dlist[de * CAP + j];
                int d = min(__usad((unsigned)cs, (unsigned)__float_as_int(dr.x), 0u),
                            (unsigned)(MAXD - 1));
                float2 ev = s_emb[d];
                mmx = fmaxf(mmx, dr.y + ev.x);
                mmy = fmaxf(mmy, dr.z + ev.y);
            }
            M0[dit] = fmaxf(M0[dit], cr.y + mmx);
            M1[dit] = fmaxf(M1[dit], cr.z + mmy);
        }
    }

    #pragma unroll
    for (int dit = 0; dit < 2; dit++) {
        float m0 = M0[dit], m1 = M1[dit];
        #pragma unroll
        for (int off = 16; off > 0; off >>= 1) {
            m0 = fmaxf(m0, __shfl_xor_sync(0xffffffffu, m0, off));
            m1 = fmaxf(m1, __shfl_xor_sync(0xffffffffu, m1, off));
        }
        if (lane == 0) {
            int de = dg * 16 + dit * 8 + w;
            float x0 = m0 + bs0, x1 = m1 + bs1;
            float mx = fmaxf(x0, x1);
            float e0 = expf(x0 - mx), e1 = expf(x1 - mx);
            float inv = 1.f / (e0 + e1);
            out[(ce * NENT + de) * 2 + 0] = e0 * inv;
            out[(ce * NENT + de) * 2 + 1] = e1 * inv;
        }
    }

    __threadfence();
    __syncthreads();
    if (tid == 0) {
        int old = atomicAdd(&g_done, 1);
        if (old == NENT * 8 - 1) {
            #pragma unroll 1
            for (int i = 0; i < 2 * NENT; i++) g_cnt[i] = 0;
            g_done = 0;
            __threadfence();
        }
    }
}

// ---------------- launch ----------------
extern "C" void kernel_launch(void* const* d_in, const int* in_sizes, int n_in,
                              void* d_out, int out_size) {
    const float* h    = (const float*)d_in[0];
    const void*  csp  = d_in[1];
    const void*  cent = d_in[2];
    const void*  dsp  = d_in[3];
    const void*  dent = d_in[4];
    const float* Wc   = (const float*)d_in[5];
    const float* bc   = (const float*)d_in[6];
    const float* Wd   = (const float*)d_in[7];
    const float* bd   = (const float*)d_in[8];
    const float* Wemb = (const float*)d_in[9];
    const float* Ws   = (const float*)d_in[10];
    const float* bs   = (const float*)d_in[11];
    float* out = (float*)d_out;

    k_prep<<<(2 * HH * NBP + 255) / 256, 256>>>(Wc, Wd);
    k_mention<<<2 * MM / BMM, 256>>>(h, csp, cent, dsp, dent, bc, bd, Ws, Wemb);
    k_pair<<<dim3(NENT, 8), 256>>>(bs, out);
}